// round 1
// baseline (speedup 1.0000x reference)
#include <cuda_runtime.h>
#include <cstdint>

// Problem constants (from reference)
#define NN 50000
#define EE 500000
#define QQ 100000
#define D  128
#define ED 16

// -------- scratch (device globals; no allocation allowed) --------
__device__ float g_H[(size_t)NN * D];                 // pre-conv output (both layers)
__device__ float g_X[(size_t)NN * D];                 // conv output (both layers)
__device__ float g_SCR[(size_t)NN * (D + ED + 1)];    // agg | eagg | deg (packed w/ runtime N)
__device__ int   g_e64, g_q64;                        // dtype flags for index tensors

// -------- helpers --------
__device__ __forceinline__ void red4(float* p, float4 v) {
    asm volatile("red.global.add.v4.f32 [%0], {%1,%2,%3,%4};"
                 :: "l"(p), "f"(v.x), "f"(v.y), "f"(v.z), "f"(v.w) : "memory");
}

// Detect whether the int tensors are int64 (high 32-bit words all zero) or int32.
__global__ void detect_kernel(const int* __restrict__ ei, const int* __restrict__ eli) {
    if (threadIdx.x == 0 && blockIdx.x == 0) {
        int a = 0, b = 0;
        for (int i = 0; i < 128; i++) { a |= ei[2 * i + 1]; b |= eli[2 * i + 1]; }
        g_e64 = (a == 0) ? 1 : 0;
        g_q64 = (b == 0) ? 1 : 0;
    }
}

__global__ void zero_kernel(float* __restrict__ p, int n4) {
    int i = blockIdx.x * blockDim.x + threadIdx.x;
    if (i < n4) ((float4*)p)[i] = make_float4(0.f, 0.f, 0.f, 0.f);
}

// =======================================================================
// Pre-conv GEMM: C[n,128] = relu(A[n,128] @ W[128,128] + bias)
// BM=128, BN=128, BK=16, 256 threads, 8x8 register tile per thread.
// =======================================================================
__global__ __launch_bounds__(256)
void gemm_pre_kernel(const float* __restrict__ A, const float* __restrict__ W,
                     const float* __restrict__ bias, float* __restrict__ C, int n) {
    __shared__ float As[128][16];
    __shared__ float Bs[16][128];
    const int block_row = blockIdx.x * 128;
    const int tid = threadIdx.x;
    const int tx = tid & 15;      // col group (8 cols)
    const int ty = tid >> 4;      // row group (8 rows)
    float acc[8][8];
    #pragma unroll
    for (int i = 0; i < 8; i++)
        #pragma unroll
        for (int j = 0; j < 8; j++) acc[i][j] = 0.f;

    for (int k0 = 0; k0 < 128; k0 += 16) {
        #pragma unroll
        for (int l = 0; l < 2; l++) {                 // A tile: 128x16
            int id = tid + l * 256;
            int r  = id >> 2;
            int kq = (id & 3) << 2;
            int grow = block_row + r;
            float4 v = make_float4(0.f, 0.f, 0.f, 0.f);
            if (grow < n) v = *(const float4*)(A + (size_t)grow * 128 + k0 + kq);
            *(float4*)&As[r][kq] = v;
        }
        #pragma unroll
        for (int l = 0; l < 2; l++) {                 // B tile: 16x128
            int id = tid + l * 256;
            int kk = id >> 5;
            int nc = (id & 31) << 2;
            *(float4*)&Bs[kk][nc] = *(const float4*)(W + (size_t)(k0 + kk) * 128 + nc);
        }
        __syncthreads();
        #pragma unroll
        for (int kk = 0; kk < 16; kk++) {
            float a[8], b[8];
            #pragma unroll
            for (int i = 0; i < 8; i++) a[i] = As[ty * 8 + i][kk];
            #pragma unroll
            for (int j = 0; j < 8; j++) b[j] = Bs[kk][tx * 8 + j];
            #pragma unroll
            for (int i = 0; i < 8; i++)
                #pragma unroll
                for (int j = 0; j < 8; j++) acc[i][j] += a[i] * b[j];
        }
        __syncthreads();
    }
    #pragma unroll
    for (int i = 0; i < 8; i++) {
        int grow = block_row + ty * 8 + i;
        if (grow < n) {
            #pragma unroll
            for (int j = 0; j < 8; j += 4) {
                int nc = tx * 8 + j;
                float4 v;
                v.x = fmaxf(acc[i][j + 0] + bias[nc + 0], 0.f);
                v.y = fmaxf(acc[i][j + 1] + bias[nc + 1], 0.f);
                v.z = fmaxf(acc[i][j + 2] + bias[nc + 2], 0.f);
                v.w = fmaxf(acc[i][j + 3] + bias[nc + 3], 0.f);
                *(float4*)(C + (size_t)grow * 128 + nc) = v;
            }
        }
    }
}

// =======================================================================
// Scatter: per edge e (warp-mapped):
//   agg[dst] += h[src]   (128 floats, one float4 per lane)
//   FIRST only: eagg[dst] += ef[e] (16 floats), deg[dst] += 1
// =======================================================================
template <bool FIRST>
__global__ __launch_bounds__(256)
void scatter_kernel(const float* __restrict__ H, const void* __restrict__ ei,
                    const float* __restrict__ ef, int E, int n) {
    float* AGG  = g_SCR;
    float* EAGG = g_SCR + (size_t)n * 128;
    float* DEG  = g_SCR + (size_t)n * 144;
    int w    = (blockIdx.x * blockDim.x + threadIdx.x) >> 5;
    int lane = threadIdx.x & 31;
    if (w >= E) return;
    int s = 0, d = 0;
    if (lane == 0) {
        if (g_e64) {
            s = (int)((const long long*)ei)[w];
            d = (int)((const long long*)ei)[(size_t)E + w];
        } else {
            s = ((const int*)ei)[w];
            d = ((const int*)ei)[(size_t)E + w];
        }
    }
    s = __shfl_sync(0xffffffffu, s, 0);
    d = __shfl_sync(0xffffffffu, d, 0);
    float4 v = *(const float4*)(H + (size_t)s * 128 + lane * 4);
    red4(AGG + (size_t)d * 128 + lane * 4, v);
    if (FIRST) {
        if (lane < 4) {
            float4 e4 = *(const float4*)(ef + (size_t)w * 16 + lane * 4);
            red4(EAGG + (size_t)d * 16 + lane * 4, e4);
        }
        if (lane == 4) atomicAdd(DEG + d, 1.0f);
    }
}

// =======================================================================
// Post-conv GEMM: out[v] = act( [deg*h | agg | eagg | deg | 0pad](288) @ Wpost )
// Wpost rows: 0..271 = msg_W, 272 = msg_b, 273..287 = 0.
// =======================================================================
template <bool RELU>
__global__ __launch_bounds__(256)
void gemm_post_kernel(const float* __restrict__ H, const float* __restrict__ msgW,
                      const float* __restrict__ msgb, float* __restrict__ C, int n) {
    const float* AGG  = g_SCR;
    const float* EAGG = g_SCR + (size_t)n * 128;
    const float* DEG  = g_SCR + (size_t)n * 144;
    __shared__ float As[128][16];
    __shared__ float Bs[16][128];
    const int block_row = blockIdx.x * 128;
    const int tid = threadIdx.x;
    const int tx = tid & 15;
    const int ty = tid >> 4;
    float acc[8][8];
    #pragma unroll
    for (int i = 0; i < 8; i++)
        #pragma unroll
        for (int j = 0; j < 8; j++) acc[i][j] = 0.f;

    for (int t = 0; t < 18; t++) {
        const int k0 = t * 16;
        #pragma unroll
        for (int l = 0; l < 2; l++) {
            int id = tid + l * 256;
            int r  = id >> 2;
            int kq = (id & 3) << 2;
            int grow = block_row + r;
            float4 v = make_float4(0.f, 0.f, 0.f, 0.f);
            if (grow < n) {
                if (k0 < 128) {
                    v = *(const float4*)(H + (size_t)grow * 128 + k0 + kq);
                    float dg = DEG[grow];
                    v.x *= dg; v.y *= dg; v.z *= dg; v.w *= dg;
                } else if (k0 < 256) {
                    v = *(const float4*)(AGG + (size_t)grow * 128 + (k0 - 128) + kq);
                } else if (k0 == 256) {
                    v = *(const float4*)(EAGG + (size_t)grow * 16 + kq);
                } else {                     // k0 == 272: col 272 = deg, rest 0
                    if (kq == 0) v.x = DEG[grow];
                }
            }
            *(float4*)&As[r][kq] = v;
        }
        #pragma unroll
        for (int l = 0; l < 2; l++) {
            int id = tid + l * 256;
            int kk = id >> 5;
            int nc = (id & 31) << 2;
            int k = k0 + kk;
            float4 v = make_float4(0.f, 0.f, 0.f, 0.f);
            if (k < 272)       v = *(const float4*)(msgW + (size_t)k * 128 + nc);
            else if (k == 272) v = *(const float4*)(msgb + nc);
            *(float4*)&Bs[kk][nc] = v;
        }
        __syncthreads();
        #pragma unroll
        for (int kk = 0; kk < 16; kk++) {
            float a[8], b[8];
            #pragma unroll
            for (int i = 0; i < 8; i++) a[i] = As[ty * 8 + i][kk];
            #pragma unroll
            for (int j = 0; j < 8; j++) b[j] = Bs[kk][tx * 8 + j];
            #pragma unroll
            for (int i = 0; i < 8; i++)
                #pragma unroll
                for (int j = 0; j < 8; j++) acc[i][j] += a[i] * b[j];
        }
        __syncthreads();
    }
    #pragma unroll
    for (int i = 0; i < 8; i++) {
        int grow = block_row + ty * 8 + i;
        if (grow < n) {
            #pragma unroll
            for (int j = 0; j < 8; j += 4) {
                int nc = tx * 8 + j;
                float4 v;
                v.x = acc[i][j + 0]; v.y = acc[i][j + 1];
                v.z = acc[i][j + 2]; v.w = acc[i][j + 3];
                if (RELU) {
                    v.x = fmaxf(v.x, 0.f); v.y = fmaxf(v.y, 0.f);
                    v.z = fmaxf(v.z, 0.f); v.w = fmaxf(v.w, 0.f);
                }
                *(float4*)(C + (size_t)grow * 128 + nc) = v;
            }
        }
    }
}

// =======================================================================
// Head: pred[q,:] = concat(X[i0], X[i1]) @ lp_W + lp_b   (one warp / query)
// =======================================================================
__global__ __launch_bounds__(256)
void head_kernel(const float* __restrict__ X, const void* __restrict__ eli,
                 const float* __restrict__ lpW, const float* __restrict__ lpb,
                 float* __restrict__ out, int Q) {
    int w    = (blockIdx.x * blockDim.x + threadIdx.x) >> 5;
    int lane = threadIdx.x & 31;
    if (w >= Q) return;
    // per-lane weights: rows 4*lane..4*lane+3 (first node) & +128 (second node)
    float2 wa[4], wb[4];
    #pragma unroll
    for (int i = 0; i < 4; i++) {
        wa[i] = *(const float2*)(lpW + (size_t)(4 * lane + i) * 2);
        wb[i] = *(const float2*)(lpW + (size_t)(128 + 4 * lane + i) * 2);
    }
    int i0 = 0, i1 = 0;
    if (lane == 0) {
        if (g_q64) {
            i0 = (int)((const long long*)eli)[w];
            i1 = (int)((const long long*)eli)[(size_t)Q + w];
        } else {
            i0 = ((const int*)eli)[w];
            i1 = ((const int*)eli)[(size_t)Q + w];
        }
    }
    i0 = __shfl_sync(0xffffffffu, i0, 0);
    i1 = __shfl_sync(0xffffffffu, i1, 0);
    float4 a = *(const float4*)(X + (size_t)i0 * 128 + lane * 4);
    float4 b = *(const float4*)(X + (size_t)i1 * 128 + lane * 4);
    float p0 = a.x * wa[0].x + a.y * wa[1].x + a.z * wa[2].x + a.w * wa[3].x
             + b.x * wb[0].x + b.y * wb[1].x + b.z * wb[2].x + b.w * wb[3].x;
    float p1 = a.x * wa[0].y + a.y * wa[1].y + a.z * wa[2].y + a.w * wa[3].y
             + b.x * wb[0].y + b.y * wb[1].y + b.z * wb[2].y + b.w * wb[3].y;
    #pragma unroll
    for (int off = 16; off; off >>= 1) {
        p0 += __shfl_down_sync(0xffffffffu, p0, off);
        p1 += __shfl_down_sync(0xffffffffu, p1, off);
    }
    if (lane == 0) {
        out[(size_t)2 * w + 0] = p0 + lpb[0];
        out[(size_t)2 * w + 1] = p1 + lpb[1];
    }
}

// =======================================================================
// Launch
// =======================================================================
extern "C" void kernel_launch(void* const* d_in, const int* in_sizes, int n_in,
                              void* d_out, int out_size) {
    const float* node_feature = (const float*)d_in[0];
    const void*  edge_index   = d_in[1];
    const float* edge_feature = (const float*)d_in[2];
    const void*  eli          = d_in[3];
    const float* c1_pre_W = (const float*)d_in[4];
    const float* c1_pre_b = (const float*)d_in[5];
    const float* c1_msg_W = (const float*)d_in[6];
    const float* c1_msg_b = (const float*)d_in[7];
    const float* c2_pre_W = (const float*)d_in[8];
    const float* c2_pre_b = (const float*)d_in[9];
    const float* c2_msg_W = (const float*)d_in[10];
    const float* c2_msg_b = (const float*)d_in[11];
    const float* lp_W     = (const float*)d_in[12];
    const float* lp_b     = (const float*)d_in[13];
    float* out = (float*)d_out;

    const int N = in_sizes[0] / D;
    const int E = in_sizes[1] / 2;
    const int Q = in_sizes[3] / 2;

    float *H, *X, *SCR;
    cudaGetSymbolAddress((void**)&H,   g_H);
    cudaGetSymbolAddress((void**)&X,   g_X);
    cudaGetSymbolAddress((void**)&SCR, g_SCR);

    const int gemm_blocks = (N + 127) / 128;
    const int scat_blocks = (E + 7) / 8;          // 8 warps/block, 1 edge/warp
    const int head_blocks = (Q + 7) / 8;
    const int zero_all4  = (N * (D + ED + 1)) / 4;
    const int zero_agg4  = (N * D) / 4;

    // dtype detection for index tensors
    detect_kernel<<<1, 32>>>((const int*)edge_index, (const int*)eli);

    // ---- layer 1 ----
    gemm_pre_kernel<<<gemm_blocks, 256>>>(node_feature, c1_pre_W, c1_pre_b, H, N);
    zero_kernel<<<(zero_all4 + 255) / 256, 256>>>(SCR, zero_all4);
    scatter_kernel<true><<<scat_blocks, 256>>>(H, edge_index, edge_feature, E, N);
    gemm_post_kernel<true><<<gemm_blocks, 256>>>(H, c1_msg_W, c1_msg_b, X, N);

    // ---- layer 2 (deg & eagg unchanged; only agg recomputed) ----
    gemm_pre_kernel<<<gemm_blocks, 256>>>(X, c2_pre_W, c2_pre_b, H, N);
    zero_kernel<<<(zero_agg4 + 255) / 256, 256>>>(SCR, zero_agg4);
    scatter_kernel<false><<<scat_blocks, 256>>>(H, edge_index, edge_feature, E, N);
    gemm_post_kernel<false><<<gemm_blocks, 256>>>(H, c2_msg_W, c2_msg_b, X, N);

    // ---- link-prediction head ----
    head_kernel<<<head_blocks, 256>>>(X, eli, lp_W, lp_b, out, Q);
}

// round 3
// speedup vs baseline: 1.9967x; 1.9967x over previous
#include <cuda_runtime.h>
#include <cstdint>

#define NN 50000
#define EE 500000
#define D  128

// ---------------- device scratch (no allocation allowed) ----------------
__device__ float g_H[(size_t)NN * D];
__device__ float g_X[(size_t)NN * D];
__device__ float g_AGG[(size_t)NN * D];
__device__ float g_EAGG[(size_t)NN * 16];
__device__ float g_DEG[NN];
__device__ int   g_cnt[NN], g_cur[NN];
__device__ int   g_off[NN + 1];
__device__ int   g_srce[EE], g_eid[EE];
__device__ int   g_bsum[512], g_bsum2[512];
__device__ int   g_e64, g_q64;
// Pre-transposed, tf32-converted, fragment-layout B images.
// Layout: [chunk][n*36 + kk], chunk = 32 k's, pad cols 32..35 stay zero (BSS).
__device__ float g_Bpre[2][4 * 4608];     // K=128 -> 4 chunks
__device__ float g_Bpost[2][9 * 4608];    // K=288 -> 9 chunks

// ---------------- helpers ----------------
__device__ __forceinline__ float to_tf32(float x) {
    uint32_t o;
    asm("cvt.rna.tf32.f32 %0, %1;" : "=r"(o) : "f"(x));
    return __uint_as_float(o);
}
__device__ __forceinline__ void mma_tf32(float* c, uint32_t a0, uint32_t a1,
                                         uint32_t a2, uint32_t a3,
                                         uint32_t b0, uint32_t b1) {
    asm volatile(
        "mma.sync.aligned.m16n8k8.row.col.f32.tf32.tf32.f32 "
        "{%0,%1,%2,%3}, {%4,%5,%6,%7}, {%8,%9}, {%0,%1,%2,%3};"
        : "+f"(c[0]), "+f"(c[1]), "+f"(c[2]), "+f"(c[3])
        : "r"(a0), "r"(a1), "r"(a2), "r"(a3), "r"(b0), "r"(b1));
}

// ---------------- misc small kernels ----------------
__global__ void detect_kernel(const int* __restrict__ ei, const int* __restrict__ eli) {
    if (threadIdx.x == 0 && blockIdx.x == 0) {
        int a = 0, b = 0;
        for (int i = 0; i < 128; i++) { a |= ei[2 * i + 1]; b |= eli[2 * i + 1]; }
        g_e64 = (a == 0) ? 1 : 0;
        g_q64 = (b == 0) ? 1 : 0;
    }
}
__global__ void zero_cc_kernel(int n) {
    int i = blockIdx.x * blockDim.x + threadIdx.x;
    if (i < n) { g_cnt[i] = 0; g_cur[i] = 0; }
}
// Build B image: value at (k, n) -> img[(k>>5)*4608 + n*36 + (k&31)], tf32-rounded.
// Row K_eff (if bias given) carries the bias; rows beyond stay zero (BSS).
__global__ void prep_b_kernel(const float* __restrict__ W, const float* __restrict__ bias,
                              float* __restrict__ img, int K_eff, int K_img) {
    int idx = blockIdx.x * blockDim.x + threadIdx.x;
    if (idx >= 128 * K_img) return;
    int n = idx & 127;
    int k = idx >> 7;
    float v = 0.f;
    if (k < K_eff) v = W[(size_t)k * 128 + n];
    else if (k == K_eff && bias != nullptr) v = bias[n];
    img[(size_t)(k >> 5) * 4608 + n * 36 + (k & 31)] = to_tf32(v);
}

// ---------------- CSR build ----------------
__global__ void hist_kernel(const void* __restrict__ ei, int E) {
    int e = blockIdx.x * blockDim.x + threadIdx.x;
    if (e >= E) return;
    int d = g_e64 ? (int)((const long long*)ei)[(size_t)E + e] : ((const int*)ei)[(size_t)E + e];
    atomicAdd(&g_cnt[d], 1);
}
__global__ void scan1_kernel(int n) {
    __shared__ int s[256];
    int idx = blockIdx.x * 256 + threadIdx.x;
    int v = (idx < n) ? g_cnt[idx] : 0;
    s[threadIdx.x] = v; __syncthreads();
    #pragma unroll
    for (int o = 1; o < 256; o <<= 1) {
        int t = (threadIdx.x >= o) ? s[threadIdx.x - o] : 0;
        __syncthreads(); s[threadIdx.x] += t; __syncthreads();
    }
    if (idx < n) g_off[idx] = s[threadIdx.x] - v;
    if (threadIdx.x == 255) g_bsum[blockIdx.x] = s[255];
}
__global__ void scan2_kernel(int nb) {
    __shared__ int s[512];
    int v0 = (threadIdx.x < nb) ? g_bsum[threadIdx.x] : 0;
    int v1 = (threadIdx.x + 256 < nb) ? g_bsum[threadIdx.x + 256] : 0;
    s[threadIdx.x] = v0; s[threadIdx.x + 256] = v1; __syncthreads();
    if (threadIdx.x == 0) {
        int run = 0;
        for (int i = 0; i < 512; i++) { int t = s[i]; s[i] = run; run += t; }
    }
    __syncthreads();
    g_bsum2[threadIdx.x] = s[threadIdx.x];
    g_bsum2[threadIdx.x + 256] = s[threadIdx.x + 256];
}
__global__ void scan3_kernel(int n, int E) {
    int idx = blockIdx.x * blockDim.x + threadIdx.x;
    if (idx < n) {
        g_off[idx] += g_bsum2[idx >> 8];
        g_DEG[idx] = (float)g_cnt[idx];
    }
    if (idx == n) g_off[n] = E;
}
__global__ void fill_kernel(const void* __restrict__ ei, int E) {
    int e = blockIdx.x * blockDim.x + threadIdx.x;
    if (e >= E) return;
    int s, d;
    if (g_e64) {
        s = (int)((const long long*)ei)[e];
        d = (int)((const long long*)ei)[(size_t)E + e];
    } else {
        s = ((const int*)ei)[e];
        d = ((const int*)ei)[(size_t)E + e];
    }
    int pos = g_off[d] + atomicAdd(&g_cur[d], 1);
    g_srce[pos] = s;
    g_eid[pos]  = e;
}
__global__ __launch_bounds__(256)
void eagg_kernel(const float* __restrict__ ef, int n) {
    int w = (blockIdx.x * blockDim.x + threadIdx.x) >> 5;
    int lane = threadIdx.x & 31;
    if (w >= n) return;
    int rs = g_off[w], re = g_off[w + 1];
    float acc = 0.f;
    for (int j = rs; j < re; j++) {
        int e = g_eid[j];
        if (lane < 16) acc += __ldg(ef + (size_t)e * 16 + lane);
    }
    if (lane < 16) g_EAGG[(size_t)w * 16 + lane] = acc;
}

// ---------------- aggregation gather (atomic-free) ----------------
__global__ __launch_bounds__(256)
void gather_agg_kernel(const float* __restrict__ H, int n) {
    int w = (blockIdx.x * blockDim.x + threadIdx.x) >> 5;
    int lane = threadIdx.x & 31;
    if (w >= n) return;
    int rs = g_off[w], re = g_off[w + 1];
    float4 a0 = make_float4(0.f, 0.f, 0.f, 0.f);
    float4 a1 = make_float4(0.f, 0.f, 0.f, 0.f);
    const float* base = H + (size_t)lane * 4;
    int j = rs;
    for (; j + 1 < re; j += 2) {
        int s0 = __ldg(&g_srce[j]), s1 = __ldg(&g_srce[j + 1]);
        float4 v0 = *(const float4*)(base + (size_t)s0 * 128);
        float4 v1 = *(const float4*)(base + (size_t)s1 * 128);
        a0.x += v0.x; a0.y += v0.y; a0.z += v0.z; a0.w += v0.w;
        a1.x += v1.x; a1.y += v1.y; a1.z += v1.z; a1.w += v1.w;
    }
    if (j < re) {
        int s0 = __ldg(&g_srce[j]);
        float4 v0 = *(const float4*)(base + (size_t)s0 * 128);
        a0.x += v0.x; a0.y += v0.y; a0.z += v0.z; a0.w += v0.w;
    }
    a0.x += a1.x; a0.y += a1.y; a0.z += a1.z; a0.w += a1.w;
    *(float4*)(g_AGG + (size_t)w * 128 + lane * 4) = a0;
}

// ---------------- tf32 mma.sync GEMM ----------------
// MODE 0: pre-conv  (K=128, epilogue relu(x + bias))
// MODE 1: post-conv (stitched K=288, relu; bias folded via deg column)
// MODE 2: post-conv (stitched K=288, no relu)
// Block tile 128x128, 8 warps, warp tile 64x32, BK=32, pad-36 SMEM rows.
template <int MODE>
__global__ __launch_bounds__(256)
void gemm_mma_kernel(const float* __restrict__ A, const float* __restrict__ Bimg,
                     const float* __restrict__ bias, float* __restrict__ Cout, int n) {
    __shared__ __align__(16) float As[128 * 36];
    __shared__ __align__(16) float Bs[128 * 36];
    const int tid = threadIdx.x, lane = tid & 31, wid = tid >> 5;
    const int g = lane >> 2, tg = lane & 3;
    const int wr = (wid & 1) * 64, wc = (wid >> 1) * 32;
    const int block_row = blockIdx.x * 128;
    const int CHUNKS = (MODE == 0) ? 4 : 9;

    float acc[4][4][4];
    #pragma unroll
    for (int t = 0; t < 4; t++)
        #pragma unroll
        for (int u = 0; u < 4; u++)
            #pragma unroll
            for (int v = 0; v < 4; v++) acc[t][u][v] = 0.f;

    for (int c = 0; c < CHUNKS; c++) {
        const int k0 = c * 32;
        // ---- stage A (tf32-convert on the fly) ----
        #pragma unroll
        for (int l = 0; l < 4; l++) {
            int i = tid + l * 256;            // 1024 float4 slots = 128 rows x 8
            int r = i >> 3, kk = (i & 7) << 2;
            int grow = block_row + r, gk = k0 + kk;
            float4 v = make_float4(0.f, 0.f, 0.f, 0.f);
            if (grow < n) {
                if (MODE == 0) {
                    v = *(const float4*)(A + (size_t)grow * 128 + gk);
                } else {
                    if (gk < 128) {
                        v = *(const float4*)(A + (size_t)grow * 128 + gk);
                        const float dg = g_DEG[grow];
                        v.x *= dg; v.y *= dg; v.z *= dg; v.w *= dg;
                    } else if (gk < 256) {
                        v = *(const float4*)(g_AGG + (size_t)grow * 128 + (gk - 128));
                    } else if (gk < 272) {
                        v = *(const float4*)(g_EAGG + (size_t)grow * 16 + (gk - 256));
                    } else if (gk == 272) {
                        v.x = g_DEG[grow];
                    }
                }
            }
            v.x = to_tf32(v.x); v.y = to_tf32(v.y);
            v.z = to_tf32(v.z); v.w = to_tf32(v.w);
            *(float4*)&As[r * 36 + kk] = v;
        }
        // ---- stage B (image already tf32 + fragment layout; straight copy) ----
        {
            const float4* src = (const float4*)(Bimg + (size_t)c * 4608);
            float4* dst = (float4*)Bs;
            #pragma unroll
            for (int l = 0; l < 5; l++) {
                int i = tid + l * 256;
                if (i < 1152) dst[i] = src[i];
            }
        }
        __syncthreads();
        // ---- 4 k8-steps of mma ----
        #pragma unroll
        for (int ks = 0; ks < 4; ks++) {
            const int kb = ks * 8;
            uint32_t bfr[4][2];
            #pragma unroll
            for (int u = 0; u < 4; u++) {
                const int nn = wc + u * 8 + g;
                bfr[u][0] = __float_as_uint(Bs[nn * 36 + kb + tg]);
                bfr[u][1] = __float_as_uint(Bs[nn * 36 + kb + tg + 4]);
            }
            #pragma unroll
            for (int t = 0; t < 4; t++) {
                const int r0 = wr + t * 16 + g, r1 = r0 + 8;
                uint32_t a0 = __float_as_uint(As[r0 * 36 + kb + tg]);
                uint32_t a1 = __float_as_uint(As[r1 * 36 + kb + tg]);
                uint32_t a2 = __float_as_uint(As[r0 * 36 + kb + tg + 4]);
                uint32_t a3 = __float_as_uint(As[r1 * 36 + kb + tg + 4]);
                #pragma unroll
                for (int u = 0; u < 4; u++)
                    mma_tf32(acc[t][u], a0, a1, a2, a3, bfr[u][0], bfr[u][1]);
            }
        }
        __syncthreads();
    }
    // ---- epilogue ----
    #pragma unroll
    for (int t = 0; t < 4; t++) {
        const int r0 = block_row + wr + t * 16 + g, r1 = r0 + 8;
        #pragma unroll
        for (int u = 0; u < 4; u++) {
            const int col = wc + u * 8 + tg * 2;
            float2 v0 = make_float2(acc[t][u][0], acc[t][u][1]);
            float2 v1 = make_float2(acc[t][u][2], acc[t][u][3]);
            if (MODE == 0) {
                float2 b2 = *(const float2*)(bias + col);
                v0.x = fmaxf(v0.x + b2.x, 0.f); v0.y = fmaxf(v0.y + b2.y, 0.f);
                v1.x = fmaxf(v1.x + b2.x, 0.f); v1.y = fmaxf(v1.y + b2.y, 0.f);
            } else if (MODE == 1) {
                v0.x = fmaxf(v0.x, 0.f); v0.y = fmaxf(v0.y, 0.f);
                v1.x = fmaxf(v1.x, 0.f); v1.y = fmaxf(v1.y, 0.f);
            }
            if (r0 < n) *(float2*)(Cout + (size_t)r0 * 128 + col) = v0;
            if (r1 < n) *(float2*)(Cout + (size_t)r1 * 128 + col) = v1;
        }
    }
}

// ---------------- link-prediction head ----------------
__global__ __launch_bounds__(256)
void head_kernel(const float* __restrict__ X, const void* __restrict__ eli,
                 const float* __restrict__ lpW, const float* __restrict__ lpb,
                 float* __restrict__ out, int Q) {
    int w = (blockIdx.x * blockDim.x + threadIdx.x) >> 5;
    int lane = threadIdx.x & 31;
    if (w >= Q) return;
    float2 wa[4], wb[4];
    #pragma unroll
    for (int i = 0; i < 4; i++) {
        wa[i] = *(const float2*)(lpW + (size_t)(4 * lane + i) * 2);
        wb[i] = *(const float2*)(lpW + (size_t)(128 + 4 * lane + i) * 2);
    }
    int i0 = 0, i1 = 0;
    if (lane == 0) {
        if (g_q64) {
            i0 = (int)((const long long*)eli)[w];
            i1 = (int)((const long long*)eli)[(size_t)Q + w];
        } else {
            i0 = ((const int*)eli)[w];
            i1 = ((const int*)eli)[(size_t)Q + w];
        }
    }
    i0 = __shfl_sync(0xffffffffu, i0, 0);
    i1 = __shfl_sync(0xffffffffu, i1, 0);
    float4 a = *(const float4*)(X + (size_t)i0 * 128 + lane * 4);
    float4 b = *(const float4*)(X + (size_t)i1 * 128 + lane * 4);
    float p0 = a.x * wa[0].x + a.y * wa[1].x + a.z * wa[2].x + a.w * wa[3].x
             + b.x * wb[0].x + b.y * wb[1].x + b.z * wb[2].x + b.w * wb[3].x;
    float p1 = a.x * wa[0].y + a.y * wa[1].y + a.z * wa[2].y + a.w * wa[3].y
             + b.x * wb[0].y + b.y * wb[1].y + b.z * wb[2].y + b.w * wb[3].y;
    #pragma unroll
    for (int off = 16; off; off >>= 1) {
        p0 += __shfl_down_sync(0xffffffffu, p0, off);
        p1 += __shfl_down_sync(0xffffffffu, p1, off);
    }
    if (lane == 0) {
        out[(size_t)2 * w + 0] = p0 + lpb[0];
        out[(size_t)2 * w + 1] = p1 + lpb[1];
    }
}

// ---------------- launch ----------------
extern "C" void kernel_launch(void* const* d_in, const int* in_sizes, int n_in,
                              void* d_out, int out_size) {
    const float* node_feature = (const float*)d_in[0];
    const void*  edge_index   = d_in[1];
    const float* edge_feature = (const float*)d_in[2];
    const void*  eli          = d_in[3];
    const float* c1_pre_W = (const float*)d_in[4];
    const float* c1_pre_b = (const float*)d_in[5];
    const float* c1_msg_W = (const float*)d_in[6];
    const float* c1_msg_b = (const float*)d_in[7];
    const float* c2_pre_W = (const float*)d_in[8];
    const float* c2_pre_b = (const float*)d_in[9];
    const float* c2_msg_W = (const float*)d_in[10];
    const float* c2_msg_b = (const float*)d_in[11];
    const float* lp_W     = (const float*)d_in[12];
    const float* lp_b     = (const float*)d_in[13];
    float* out = (float*)d_out;

    const int N = in_sizes[0] / D;
    const int E = in_sizes[1] / 2;
    const int Q = in_sizes[3] / 2;

    float *H, *X, *Bpre, *Bpost;
    cudaGetSymbolAddress((void**)&H, g_H);
    cudaGetSymbolAddress((void**)&X, g_X);
    cudaGetSymbolAddress((void**)&Bpre, g_Bpre);
    cudaGetSymbolAddress((void**)&Bpost, g_Bpost);
    float* Bpre1  = Bpre;
    float* Bpre2  = Bpre + 4 * 4608;
    float* Bpost1 = Bpost;
    float* Bpost2 = Bpost + 9 * 4608;

    const int gemm_blocks  = (N + 127) / 128;
    const int warp8_blocks = (N + 7) / 8;
    const int edge_blocks  = (E + 255) / 256;
    const int nb = (N + 255) / 256;

    detect_kernel<<<1, 32>>>((const int*)edge_index, (const int*)eli);

    // B operand images
    prep_b_kernel<<<(128 * 128 + 255) / 256, 256>>>(c1_pre_W, nullptr, Bpre1, 128, 128);
    prep_b_kernel<<<(128 * 128 + 255) / 256, 256>>>(c2_pre_W, nullptr, Bpre2, 128, 128);
    prep_b_kernel<<<(128 * 288 + 255) / 256, 256>>>(c1_msg_W, c1_msg_b, Bpost1, 272, 288);
    prep_b_kernel<<<(128 * 288 + 255) / 256, 256>>>(c2_msg_W, c2_msg_b, Bpost2, 272, 288);

    // CSR build (deg + eagg are layer-invariant)
    zero_cc_kernel<<<nb, 256>>>(N);
    hist_kernel<<<edge_blocks, 256>>>(edge_index, E);
    scan1_kernel<<<nb, 256>>>(N);
    scan2_kernel<<<1, 256>>>(nb);
    scan3_kernel<<<(N + 256) / 256, 256>>>(N, E);
    fill_kernel<<<edge_blocks, 256>>>(edge_index, E);
    eagg_kernel<<<warp8_blocks, 256>>>(edge_feature, N);

    // layer 1
    gemm_mma_kernel<0><<<gemm_blocks, 256>>>(node_feature, Bpre1, c1_pre_b, H, N);
    gather_agg_kernel<<<warp8_blocks, 256>>>(H, N);
    gemm_mma_kernel<1><<<gemm_blocks, 256>>>(H, Bpost1, nullptr, X, N);

    // layer 2
    gemm_mma_kernel<0><<<gemm_blocks, 256>>>(X, Bpre2, c2_pre_b, H, N);
    gather_agg_kernel<<<warp8_blocks, 256>>>(H, N);
    gemm_mma_kernel<2><<<gemm_blocks, 256>>>(H, Bpost2, nullptr, X, N);

    head_kernel<<<(Q + 7) / 8, 256>>>(X, eli, lp_W, lp_b, out, Q);
}

// round 4
// speedup vs baseline: 2.4016x; 1.2028x over previous
#include <cuda_runtime.h>
#include <cstdint>

#define NN 50000
#define EE 500000
#define D  128

// ---------------- device scratch (no allocation allowed) ----------------
__device__ float g_H[(size_t)NN * D];            // pre-conv output
__device__ float g_HD[(size_t)NN * D];           // deg * H (for post-GEMM A)
__device__ float g_X[(size_t)NN * D];            // conv output
__device__ float g_AGG[(size_t)NN * D];          // gathered neighbor sum
__device__ float g_TAIL[(size_t)NN * 32];        // [eagg(16) | deg | 0...]
__device__ float g_DEG[NN];
__device__ int   g_cnt[NN], g_cur[NN];
__device__ int   g_off[NN + 1];
__device__ int   g_srce[EE], g_eid[EE];
__device__ int   g_bsum[512], g_bsum2[512];
__device__ int   g_e64, g_q64;
// Pre-transposed, tf32-converted, fragment-layout B images.
// Layout: [chunk][n*36 + kk], chunk = 32 k's, pad cols 32..35 zero (BSS).
__device__ float g_Bpre[2][4 * 4608];     // K=128 -> 4 chunks
__device__ float g_Bpost[2][9 * 4608];    // K=288 -> 9 chunks

// ---------------- helpers ----------------
__device__ __forceinline__ uint32_t f2tf(float x) {
    uint32_t o;
    asm("cvt.rna.tf32.f32 %0, %1;" : "=r"(o) : "f"(x));
    return o;
}
__device__ __forceinline__ float to_tf32(float x) { return __uint_as_float(f2tf(x)); }
__device__ __forceinline__ void mma_tf32(float* c, uint32_t a0, uint32_t a1,
                                         uint32_t a2, uint32_t a3,
                                         uint32_t b0, uint32_t b1) {
    asm volatile(
        "mma.sync.aligned.m16n8k8.row.col.f32.tf32.tf32.f32 "
        "{%0,%1,%2,%3}, {%4,%5,%6,%7}, {%8,%9}, {%0,%1,%2,%3};"
        : "+f"(c[0]), "+f"(c[1]), "+f"(c[2]), "+f"(c[3])
        : "r"(a0), "r"(a1), "r"(a2), "r"(a3), "r"(b0), "r"(b1));
}
__device__ __forceinline__ void cpa16(uint32_t dst, const void* src, int sz) {
    asm volatile("cp.async.cg.shared.global [%0], [%1], 16, %2;"
                 :: "r"(dst), "l"(src), "r"(sz) : "memory");
}
#define CP_COMMIT() asm volatile("cp.async.commit_group;" ::: "memory")
#define CP_WAIT1()  asm volatile("cp.async.wait_group 1;" ::: "memory")

// ---------------- fused detect + zero ----------------
__global__ void detect_zero_kernel(const int* __restrict__ ei, const int* __restrict__ eli, int n) {
    int i = blockIdx.x * blockDim.x + threadIdx.x;
    if (i < n) { g_cnt[i] = 0; g_cur[i] = 0; }
    if (i == 0) {
        int a = 0, b = 0;
        for (int j = 0; j < 128; j++) { a |= ei[2 * j + 1]; b |= eli[2 * j + 1]; }
        g_e64 = (a == 0) ? 1 : 0;
        g_q64 = (b == 0) ? 1 : 0;
    }
}

// ---------------- fused B-image prep (all 4 weight matrices) ----------------
// img[(k>>5)*4608 + n*36 + (k&31)] = tf32(value at (k, n)); bias at row K_eff.
__device__ __forceinline__ void prep_one(const float* W, const float* bias,
                                         float* img, int K_eff, int idx) {
    int n = idx & 127;
    int k = idx >> 7;
    float v = 0.f;
    if (k < K_eff) v = W[(size_t)k * 128 + n];
    else if (k == K_eff && bias != nullptr) v = bias[n];
    img[(size_t)(k >> 5) * 4608 + n * 36 + (k & 31)] = to_tf32(v);
}
__global__ void prep_all_kernel(const float* W1, const float* W2,
                                const float* W3, const float* b3,
                                const float* W4, const float* b4,
                                float* img1, float* img2, float* img3, float* img4) {
    int idx = blockIdx.x * blockDim.x + threadIdx.x;
    if (idx < 16384)       prep_one(W1, nullptr, img1, 128, idx);
    else if (idx < 32768)  prep_one(W2, nullptr, img2, 128, idx - 16384);
    else if (idx < 69632)  prep_one(W3, b3, img3, 272, idx - 32768);
    else if (idx < 106496) prep_one(W4, b4, img4, 272, idx - 69632);
}

// ---------------- CSR build ----------------
__global__ void hist_kernel(const void* __restrict__ ei, int E) {
    int e = blockIdx.x * blockDim.x + threadIdx.x;
    if (e >= E) return;
    int d = g_e64 ? (int)((const long long*)ei)[(size_t)E + e] : ((const int*)ei)[(size_t)E + e];
    atomicAdd(&g_cnt[d], 1);
}
__global__ void scan1_kernel(int n) {
    __shared__ int s[256];
    int idx = blockIdx.x * 256 + threadIdx.x;
    int v = (idx < n) ? g_cnt[idx] : 0;
    s[threadIdx.x] = v; __syncthreads();
    #pragma unroll
    for (int o = 1; o < 256; o <<= 1) {
        int t = (threadIdx.x >= o) ? s[threadIdx.x - o] : 0;
        __syncthreads(); s[threadIdx.x] += t; __syncthreads();
    }
    if (idx < n) g_off[idx] = s[threadIdx.x] - v;
    if (threadIdx.x == 255) g_bsum[blockIdx.x] = s[255];
}
__global__ void scan2_kernel(int nb) {
    __shared__ int s[512];
    int v0 = (threadIdx.x < nb) ? g_bsum[threadIdx.x] : 0;
    int v1 = (threadIdx.x + 256 < nb) ? g_bsum[threadIdx.x + 256] : 0;
    s[threadIdx.x] = v0; s[threadIdx.x + 256] = v1; __syncthreads();
    if (threadIdx.x == 0) {
        int run = 0;
        for (int i = 0; i < 512; i++) { int t = s[i]; s[i] = run; run += t; }
    }
    __syncthreads();
    g_bsum2[threadIdx.x] = s[threadIdx.x];
    g_bsum2[threadIdx.x + 256] = s[threadIdx.x + 256];
}
__global__ void scan3_kernel(int n, int E) {
    int idx = blockIdx.x * blockDim.x + threadIdx.x;
    if (idx < n) {
        g_off[idx] += g_bsum2[idx >> 8];
        g_DEG[idx] = (float)g_cnt[idx];
    }
    if (idx == n) g_off[n] = E;
}
__global__ void fill_kernel(const void* __restrict__ ei, int E) {
    int e = blockIdx.x * blockDim.x + threadIdx.x;
    if (e >= E) return;
    int s, d;
    if (g_e64) {
        s = (int)((const long long*)ei)[e];
        d = (int)((const long long*)ei)[(size_t)E + e];
    } else {
        s = ((const int*)ei)[e];
        d = ((const int*)ei)[(size_t)E + e];
    }
    int pos = g_off[d] + atomicAdd(&g_cur[d], 1);
    g_srce[pos] = s;
    g_eid[pos]  = e;
}
// eagg + TAIL pack: TAIL[w][0..15]=eagg, [16]=deg, [17..31]=0
__global__ __launch_bounds__(256)
void eagg_tail_kernel(const float* __restrict__ ef, int n) {
    int w = (blockIdx.x * blockDim.x + threadIdx.x) >> 5;
    int lane = threadIdx.x & 31;
    if (w >= n) return;
    int rs = g_off[w], re = g_off[w + 1];
    float acc = 0.f;
    if (lane < 16) {
        for (int j = rs; j < re; j++) {
            int e = __ldg(&g_eid[j]);
            acc += __ldg(ef + (size_t)e * 16 + lane);
        }
    } else if (lane == 16) {
        acc = g_DEG[w];
    }
    g_TAIL[(size_t)w * 32 + lane] = acc;
}

// ---------------- aggregation gather (atomic-free) ----------------
__global__ __launch_bounds__(256)
void gather_agg_kernel(const float* __restrict__ H, int n) {
    int w = (blockIdx.x * blockDim.x + threadIdx.x) >> 5;
    int lane = threadIdx.x & 31;
    if (w >= n) return;
    int rs = g_off[w], re = g_off[w + 1];
    float4 a0 = make_float4(0.f, 0.f, 0.f, 0.f);
    float4 a1 = make_float4(0.f, 0.f, 0.f, 0.f);
    const float* base = H + (size_t)lane * 4;
    int j = rs;
    for (; j + 1 < re; j += 2) {
        int s0 = __ldg(&g_srce[j]), s1 = __ldg(&g_srce[j + 1]);
        float4 v0 = *(const float4*)(base + (size_t)s0 * 128);
        float4 v1 = *(const float4*)(base + (size_t)s1 * 128);
        a0.x += v0.x; a0.y += v0.y; a0.z += v0.z; a0.w += v0.w;
        a1.x += v1.x; a1.y += v1.y; a1.z += v1.z; a1.w += v1.w;
    }
    if (j < re) {
        int s0 = __ldg(&g_srce[j]);
        float4 v0 = *(const float4*)(base + (size_t)s0 * 128);
        a0.x += v0.x; a0.y += v0.y; a0.z += v0.z; a0.w += v0.w;
    }
    a0.x += a1.x; a0.y += a1.y; a0.z += a1.z; a0.w += a1.w;
    *(float4*)(g_AGG + (size_t)w * 128 + lane * 4) = a0;
}

// ---------------- tf32 mma.sync GEMM, cp.async double-buffered ----------------
// MODE 0: pre-conv  (K=128; epilogue H=relu(x+bias), HD=deg*H)
// MODE 1: post-conv (stitched K=288 from HD|AGG|TAIL, relu)
// MODE 2: post-conv (stitched K=288, no relu)
// Block 128x128, 8 warps, warp tile 64x32, BK=32, pad-36 rows, 2-stage pipeline.
#define GSMEM (4 * 4608 * 4)   // 73728 B: A0 A1 B0 B1

template <int MODE>
__device__ __forceinline__ void stage_chunk(const float* __restrict__ A,
                                            const float* __restrict__ Bimg,
                                            float* AsBuf, float* BsBuf,
                                            int c, int block_row, int n, int tid) {
    const int k0 = c * 32;
    const float* srcbase;
    int stride, off;
    if (MODE == 0)      { srcbase = A;      stride = 128; off = k0; }
    else if (k0 < 128)  { srcbase = g_HD;   stride = 128; off = k0; }
    else if (k0 < 256)  { srcbase = g_AGG;  stride = 128; off = k0 - 128; }
    else                { srcbase = g_TAIL; stride = 32;  off = 0; }
    #pragma unroll
    for (int l = 0; l < 4; l++) {
        int i = tid + l * 256;                 // 1024 = 128 rows x 8 float4
        int r = i >> 3, kq = (i & 7) << 2;
        int grow = block_row + r;
        uint32_t dst = (uint32_t)__cvta_generic_to_shared(AsBuf + r * 36 + kq);
        cpa16(dst, srcbase + (size_t)grow * stride + off + kq, grow < n ? 16 : 0);
    }
    const float4* bsrc = (const float4*)(Bimg + (size_t)c * 4608);
    #pragma unroll
    for (int l = 0; l < 5; l++) {
        int i = tid + l * 256;
        if (i < 1152) {
            uint32_t dst = (uint32_t)__cvta_generic_to_shared((float4*)BsBuf + i);
            cpa16(dst, bsrc + i, 16);
        }
    }
}

template <int MODE>
__global__ __launch_bounds__(256)
void gemm_mma_kernel(const float* __restrict__ A, const float* __restrict__ Bimg,
                     const float* __restrict__ bias, float* __restrict__ Cout,
                     float* __restrict__ Cout2, int n) {
    extern __shared__ __align__(16) float sm[];
    float* Asb[2] = { sm, sm + 4608 };
    float* Bsb[2] = { sm + 9216, sm + 13824 };
    const int tid = threadIdx.x, lane = tid & 31, wid = tid >> 5;
    const int g = lane >> 2, tg = lane & 3;
    const int wr = (wid & 1) * 64, wc = (wid >> 1) * 32;
    const int block_row = blockIdx.x * 128;
    const int CHUNKS = (MODE == 0) ? 4 : 9;

    float acc[4][4][4];
    #pragma unroll
    for (int t = 0; t < 4; t++)
        #pragma unroll
        for (int u = 0; u < 4; u++)
            #pragma unroll
            for (int v = 0; v < 4; v++) acc[t][u][v] = 0.f;

    stage_chunk<MODE>(A, Bimg, Asb[0], Bsb[0], 0, block_row, n, tid);
    CP_COMMIT();

    for (int c = 0; c < CHUNKS; c++) {
        const int cur = c & 1;
        if (c + 1 < CHUNKS)
            stage_chunk<MODE>(A, Bimg, Asb[(c + 1) & 1], Bsb[(c + 1) & 1],
                              c + 1, block_row, n, tid);
        CP_COMMIT();
        CP_WAIT1();
        __syncthreads();
        const float* As = Asb[cur];
        const float* Bs = Bsb[cur];
        #pragma unroll
        for (int ks = 0; ks < 4; ks++) {
            const int kb = ks * 8;
            uint32_t bfr[4][2];
            #pragma unroll
            for (int u = 0; u < 4; u++) {
                const int nn = wc + u * 8 + g;
                bfr[u][0] = __float_as_uint(Bs[nn * 36 + kb + tg]);
                bfr[u][1] = __float_as_uint(Bs[nn * 36 + kb + tg + 4]);
            }
            #pragma unroll
            for (int t = 0; t < 4; t++) {
                const int r0 = wr + t * 16 + g, r1 = r0 + 8;
                uint32_t a0 = f2tf(As[r0 * 36 + kb + tg]);
                uint32_t a1 = f2tf(As[r1 * 36 + kb + tg]);
                uint32_t a2 = f2tf(As[r0 * 36 + kb + tg + 4]);
                uint32_t a3 = f2tf(As[r1 * 36 + kb + tg + 4]);
                #pragma unroll
                for (int u = 0; u < 4; u++)
                    mma_tf32(acc[t][u], a0, a1, a2, a3, bfr[u][0], bfr[u][1]);
            }
        }
        __syncthreads();
    }
    // ---- epilogue ----
    #pragma unroll
    for (int t = 0; t < 4; t++) {
        const int r0 = block_row + wr + t * 16 + g, r1 = r0 + 8;
        float d0 = 0.f, d1 = 0.f;
        if (MODE == 0) {
            if (r0 < n) d0 = g_DEG[r0];
            if (r1 < n) d1 = g_DEG[r1];
        }
        #pragma unroll
        for (int u = 0; u < 4; u++) {
            const int col = wc + u * 8 + tg * 2;
            float2 v0 = make_float2(acc[t][u][0], acc[t][u][1]);
            float2 v1 = make_float2(acc[t][u][2], acc[t][u][3]);
            if (MODE == 0) {
                float2 b2 = *(const float2*)(bias + col);
                v0.x = fmaxf(v0.x + b2.x, 0.f); v0.y = fmaxf(v0.y + b2.y, 0.f);
                v1.x = fmaxf(v1.x + b2.x, 0.f); v1.y = fmaxf(v1.y + b2.y, 0.f);
                if (r0 < n) {
                    *(float2*)(Cout + (size_t)r0 * 128 + col) = v0;
                    *(float2*)(Cout2 + (size_t)r0 * 128 + col) = make_float2(v0.x * d0, v0.y * d0);
                }
                if (r1 < n) {
                    *(float2*)(Cout + (size_t)r1 * 128 + col) = v1;
                    *(float2*)(Cout2 + (size_t)r1 * 128 + col) = make_float2(v1.x * d1, v1.y * d1);
                }
            } else {
                if (MODE == 1) {
                    v0.x = fmaxf(v0.x, 0.f); v0.y = fmaxf(v0.y, 0.f);
                    v1.x = fmaxf(v1.x, 0.f); v1.y = fmaxf(v1.y, 0.f);
                }
                if (r0 < n) *(float2*)(Cout + (size_t)r0 * 128 + col) = v0;
                if (r1 < n) *(float2*)(Cout + (size_t)r1 * 128 + col) = v1;
            }
        }
    }
}

// ---------------- link-prediction head ----------------
__global__ __launch_bounds__(256)
void head_kernel(const float* __restrict__ X, const void* __restrict__ eli,
                 const float* __restrict__ lpW, const float* __restrict__ lpb,
                 float* __restrict__ out, int Q) {
    int w = (blockIdx.x * blockDim.x + threadIdx.x) >> 5;
    int lane = threadIdx.x & 31;
    if (w >= Q) return;
    float2 wa[4], wb[4];
    #pragma unroll
    for (int i = 0; i < 4; i++) {
        wa[i] = *(const float2*)(lpW + (size_t)(4 * lane + i) * 2);
        wb[i] = *(const float2*)(lpW + (size_t)(128 + 4 * lane + i) * 2);
    }
    int i0 = 0, i1 = 0;
    if (lane == 0) {
        if (g_q64) {
            i0 = (int)((const long long*)eli)[w];
            i1 = (int)((const long long*)eli)[(size_t)Q + w];
        } else {
            i0 = ((const int*)eli)[w];
            i1 = ((const int*)eli)[(size_t)Q + w];
        }
    }
    i0 = __shfl_sync(0xffffffffu, i0, 0);
    i1 = __shfl_sync(0xffffffffu, i1, 0);
    float4 a = *(const float4*)(X + (size_t)i0 * 128 + lane * 4);
    float4 b = *(const float4*)(X + (size_t)i1 * 128 + lane * 4);
    float p0 = a.x * wa[0].x + a.y * wa[1].x + a.z * wa[2].x + a.w * wa[3].x
             + b.x * wb[0].x + b.y * wb[1].x + b.z * wb[2].x + b.w * wb[3].x;
    float p1 = a.x * wa[0].y + a.y * wa[1].y + a.z * wa[2].y + a.w * wa[3].y
             + b.x * wb[0].y + b.y * wb[1].y + b.z * wb[2].y + b.w * wb[3].y;
    #pragma unroll
    for (int off = 16; off; off >>= 1) {
        p0 += __shfl_down_sync(0xffffffffu, p0, off);
        p1 += __shfl_down_sync(0xffffffffu, p1, off);
    }
    if (lane == 0) {
        out[(size_t)2 * w + 0] = p0 + lpb[0];
        out[(size_t)2 * w + 1] = p1 + lpb[1];
    }
}

// ---------------- launch ----------------
extern "C" void kernel_launch(void* const* d_in, const int* in_sizes, int n_in,
                              void* d_out, int out_size) {
    const float* node_feature = (const float*)d_in[0];
    const void*  edge_index   = d_in[1];
    const float* edge_feature = (const float*)d_in[2];
    const void*  eli          = d_in[3];
    const float* c1_pre_W = (const float*)d_in[4];
    const float* c1_pre_b = (const float*)d_in[5];
    const float* c1_msg_W = (const float*)d_in[6];
    const float* c1_msg_b = (const float*)d_in[7];
    const float* c2_pre_W = (const float*)d_in[8];
    const float* c2_pre_b = (const float*)d_in[9];
    const float* c2_msg_W = (const float*)d_in[10];
    const float* c2_msg_b = (const float*)d_in[11];
    const float* lp_W     = (const float*)d_in[12];
    const float* lp_b     = (const float*)d_in[13];
    float* out = (float*)d_out;

    const int N = in_sizes[0] / D;
    const int E = in_sizes[1] / 2;
    const int Q = in_sizes[3] / 2;

    float *H, *HD, *X, *Bpre, *Bpost;
    cudaGetSymbolAddress((void**)&H,  g_H);
    cudaGetSymbolAddress((void**)&HD, g_HD);
    cudaGetSymbolAddress((void**)&X,  g_X);
    cudaGetSymbolAddress((void**)&Bpre, g_Bpre);
    cudaGetSymbolAddress((void**)&Bpost, g_Bpost);
    float* Bpre1  = Bpre;
    float* Bpre2  = Bpre + 4 * 4608;
    float* Bpost1 = Bpost;
    float* Bpost2 = Bpost + 9 * 4608;

    static int attr_done = 0;
    if (!attr_done) {
        cudaFuncSetAttribute(gemm_mma_kernel<0>, cudaFuncAttributeMaxDynamicSharedMemorySize, GSMEM);
        cudaFuncSetAttribute(gemm_mma_kernel<1>, cudaFuncAttributeMaxDynamicSharedMemorySize, GSMEM);
        cudaFuncSetAttribute(gemm_mma_kernel<2>, cudaFuncAttributeMaxDynamicSharedMemorySize, GSMEM);
        attr_done = 1;
    }

    const int gemm_blocks  = (N + 127) / 128;
    const int warp8_blocks = (N + 7) / 8;
    const int edge_blocks  = (E + 255) / 256;
    const int nb = (N + 255) / 256;

    detect_zero_kernel<<<nb, 256>>>((const int*)edge_index, (const int*)eli, N);
    prep_all_kernel<<<(106496 + 255) / 256, 256>>>(c1_pre_W, c2_pre_W,
                                                   c1_msg_W, c1_msg_b,
                                                   c2_msg_W, c2_msg_b,
                                                   Bpre1, Bpre2, Bpost1, Bpost2);

    // CSR build (deg + eagg/TAIL are layer-invariant)
    hist_kernel<<<edge_blocks, 256>>>(edge_index, E);
    scan1_kernel<<<nb, 256>>>(N);
    scan2_kernel<<<1, 256>>>(nb);
    scan3_kernel<<<(N + 256) / 256, 256>>>(N, E);
    fill_kernel<<<edge_blocks, 256>>>(edge_index, E);
    eagg_tail_kernel<<<warp8_blocks, 256>>>(edge_feature, N);

    // layer 1
    gemm_mma_kernel<0><<<gemm_blocks, 256, GSMEM>>>(node_feature, Bpre1, c1_pre_b, H, HD, N);
    gather_agg_kernel<<<warp8_blocks, 256>>>(H, N);
    gemm_mma_kernel<1><<<gemm_blocks, 256, GSMEM>>>(H, Bpost1, nullptr, X, nullptr, N);

    // layer 2
    gemm_mma_kernel<0><<<gemm_blocks, 256, GSMEM>>>(X, Bpre2, c2_pre_b, H, HD, N);
    gather_agg_kernel<<<warp8_blocks, 256>>>(H, N);
    gemm_mma_kernel<2><<<gemm_blocks, 256, GSMEM>>>(H, Bpost2, nullptr, X, nullptr, N);

    head_kernel<<<(Q + 7) / 8, 256>>>(X, eli, lp_W, lp_b, out, Q);
}

// round 5
// speedup vs baseline: 2.5786x; 1.0737x over previous
#include <cuda_runtime.h>
#include <cstdint>

#define NN 50000
#define EE 500000
#define D  128

// ---------------- device scratch (no allocation allowed) ----------------
__device__ float g_H[(size_t)NN * D];            // pre-conv output
__device__ float g_HD[(size_t)NN * D];           // deg * H (written by gather)
__device__ float g_X[(size_t)NN * D];            // conv output
__device__ float g_AGG[(size_t)NN * D];          // gathered neighbor sum
__device__ float g_TAIL[(size_t)NN * 32];        // [eagg(16) | deg | 0...]
__device__ float g_DEG[NN];
__device__ int   g_cnt[NN], g_cur[NN];
__device__ int   g_off[NN + 1];
__device__ int   g_srce[EE], g_eid[EE];
__device__ int   g_bsum[512], g_bsum2[512];
__device__ int   g_e64, g_q64;
// Pre-transposed, tf32-converted, fragment-layout B images.
// Layout: [chunk][n*36 + kk], chunk = 32 k's, pad cols 32..35 zero (BSS).
__device__ float g_Bpre[2][4 * 4608];     // K=128 -> 4 chunks
__device__ float g_Bpost[2][9 * 4608];    // K=288 -> 9 chunks

// ---------------- helpers ----------------
__device__ __forceinline__ uint32_t f2tf(float x) {
    uint32_t o;
    asm("cvt.rna.tf32.f32 %0, %1;" : "=r"(o) : "f"(x));
    return o;
}
__device__ __forceinline__ float to_tf32(float x) { return __uint_as_float(f2tf(x)); }
__device__ __forceinline__ void mma_tf32(float* c, uint32_t a0, uint32_t a1,
                                         uint32_t a2, uint32_t a3,
                                         uint32_t b0, uint32_t b1) {
    asm volatile(
        "mma.sync.aligned.m16n8k8.row.col.f32.tf32.tf32.f32 "
        "{%0,%1,%2,%3}, {%4,%5,%6,%7}, {%8,%9}, {%0,%1,%2,%3};"
        : "+f"(c[0]), "+f"(c[1]), "+f"(c[2]), "+f"(c[3])
        : "r"(a0), "r"(a1), "r"(a2), "r"(a3), "r"(b0), "r"(b1));
}
__device__ __forceinline__ void cpa16(uint32_t dst, const void* src, int sz) {
    asm volatile("cp.async.cg.shared.global [%0], [%1], 16, %2;"
                 :: "r"(dst), "l"(src), "r"(sz) : "memory");
}
#define CP_COMMIT() asm volatile("cp.async.commit_group;" ::: "memory")
#define CP_WAIT1()  asm volatile("cp.async.wait_group 1;" ::: "memory")

// ---------------- fused detect (warp-parallel) + zero ----------------
__global__ void detect_zero_kernel(const int* __restrict__ ei, const int* __restrict__ eli, int n) {
    int i = blockIdx.x * blockDim.x + threadIdx.x;
    if (i < n) { g_cnt[i] = 0; g_cur[i] = 0; }
    if (blockIdx.x == 0 && threadIdx.x < 32) {
        int lane = threadIdx.x;
        int a = 0, b = 0;
        #pragma unroll
        for (int j = 0; j < 4; j++) {
            a |= ei[2 * (lane * 4 + j) + 1];
            b |= eli[2 * (lane * 4 + j) + 1];
        }
        unsigned ba = __ballot_sync(0xffffffffu, a != 0);
        unsigned bb = __ballot_sync(0xffffffffu, b != 0);
        if (lane == 0) {
            g_e64 = (ba == 0) ? 1 : 0;
            g_q64 = (bb == 0) ? 1 : 0;
        }
    }
}

// ---------------- fused B-image prep (all 4 weight matrices) ----------------
__device__ __forceinline__ void prep_one(const float* W, const float* bias,
                                         float* img, int K_eff, int idx) {
    int n = idx & 127;
    int k = idx >> 7;
    float v = 0.f;
    if (k < K_eff) v = W[(size_t)k * 128 + n];
    else if (k == K_eff && bias != nullptr) v = bias[n];
    img[(size_t)(k >> 5) * 4608 + n * 36 + (k & 31)] = to_tf32(v);
}
__global__ void prep_all_kernel(const float* W1, const float* W2,
                                const float* W3, const float* b3,
                                const float* W4, const float* b4,
                                float* img1, float* img2, float* img3, float* img4) {
    int idx = blockIdx.x * blockDim.x + threadIdx.x;
    if (idx < 16384)       prep_one(W1, nullptr, img1, 128, idx);
    else if (idx < 32768)  prep_one(W2, nullptr, img2, 128, idx - 16384);
    else if (idx < 69632)  prep_one(W3, b3, img3, 272, idx - 32768);
    else if (idx < 106496) prep_one(W4, b4, img4, 272, idx - 69632);
}

// ---------------- CSR build ----------------
__global__ void hist_kernel(const void* __restrict__ ei, int E) {
    int e = blockIdx.x * blockDim.x + threadIdx.x;
    if (e >= E) return;
    int d = g_e64 ? (int)((const long long*)ei)[(size_t)E + e] : ((const int*)ei)[(size_t)E + e];
    atomicAdd(&g_cnt[d], 1);
}
__global__ void scan1_kernel(int n) {
    __shared__ int s[256];
    int idx = blockIdx.x * 256 + threadIdx.x;
    int v = (idx < n) ? g_cnt[idx] : 0;
    s[threadIdx.x] = v; __syncthreads();
    #pragma unroll
    for (int o = 1; o < 256; o <<= 1) {
        int t = (threadIdx.x >= o) ? s[threadIdx.x - o] : 0;
        __syncthreads(); s[threadIdx.x] += t; __syncthreads();
    }
    if (idx < n) g_off[idx] = s[threadIdx.x] - v;
    if (threadIdx.x == 255) g_bsum[blockIdx.x] = s[255];
}
__global__ void scan2_kernel(int nb) {
    __shared__ int s[512];
    int v0 = (threadIdx.x < nb) ? g_bsum[threadIdx.x] : 0;
    int v1 = (threadIdx.x + 256 < nb) ? g_bsum[threadIdx.x + 256] : 0;
    s[threadIdx.x] = v0; s[threadIdx.x + 256] = v1; __syncthreads();
    if (threadIdx.x == 0) {
        int run = 0;
        for (int i = 0; i < 512; i++) { int t = s[i]; s[i] = run; run += t; }
    }
    __syncthreads();
    g_bsum2[threadIdx.x] = s[threadIdx.x];
    g_bsum2[threadIdx.x + 256] = s[threadIdx.x + 256];
}
__global__ void scan3_kernel(int n, int E) {
    int idx = blockIdx.x * blockDim.x + threadIdx.x;
    if (idx < n) {
        g_off[idx] += g_bsum2[idx >> 8];
        g_DEG[idx] = (float)g_cnt[idx];
    }
    if (idx == n) g_off[n] = E;
}
__global__ void fill_kernel(const void* __restrict__ ei, int E) {
    int e = blockIdx.x * blockDim.x + threadIdx.x;
    if (e >= E) return;
    int s, d;
    if (g_e64) {
        s = (int)((const long long*)ei)[e];
        d = (int)((const long long*)ei)[(size_t)E + e];
    } else {
        s = ((const int*)ei)[e];
        d = ((const int*)ei)[(size_t)E + e];
    }
    int pos = g_off[d] + atomicAdd(&g_cur[d], 1);
    g_srce[pos] = s;
    g_eid[pos]  = e;
}
// eagg + TAIL pack: TAIL[w][0..15]=eagg, [16]=deg, [17..31]=0
__global__ __launch_bounds__(256)
void eagg_tail_kernel(const float* __restrict__ ef, int n) {
    int w = (blockIdx.x * blockDim.x + threadIdx.x) >> 5;
    int lane = threadIdx.x & 31;
    if (w >= n) return;
    int rs = g_off[w], re = g_off[w + 1];
    float acc = 0.f;
    if (lane < 16) {
        for (int j = rs; j < re; j++) {
            int e = __ldg(&g_eid[j]);
            acc += __ldg(ef + (size_t)e * 16 + lane);
        }
    } else if (lane == 16) {
        acc = g_DEG[w];
    }
    g_TAIL[(size_t)w * 32 + lane] = acc;
}

// ---------------- aggregation gather (atomic-free) + HD = deg*H ----------------
__global__ __launch_bounds__(256)
void gather_agg_kernel(const float* __restrict__ H, int n) {
    int w = (blockIdx.x * blockDim.x + threadIdx.x) >> 5;
    int lane = threadIdx.x & 31;
    if (w >= n) return;
    int rs = g_off[w], re = g_off[w + 1];
    float4 a0 = make_float4(0.f, 0.f, 0.f, 0.f);
    float4 a1 = make_float4(0.f, 0.f, 0.f, 0.f);
    const float* base = H + (size_t)lane * 4;
    int j = rs;
    for (; j + 1 < re; j += 2) {
        int s0 = __ldg(&g_srce[j]), s1 = __ldg(&g_srce[j + 1]);
        float4 v0 = *(const float4*)(base + (size_t)s0 * 128);
        float4 v1 = *(const float4*)(base + (size_t)s1 * 128);
        a0.x += v0.x; a0.y += v0.y; a0.z += v0.z; a0.w += v0.w;
        a1.x += v1.x; a1.y += v1.y; a1.z += v1.z; a1.w += v1.w;
    }
    if (j < re) {
        int s0 = __ldg(&g_srce[j]);
        float4 v0 = *(const float4*)(base + (size_t)s0 * 128);
        a0.x += v0.x; a0.y += v0.y; a0.z += v0.z; a0.w += v0.w;
    }
    a0.x += a1.x; a0.y += a1.y; a0.z += a1.z; a0.w += a1.w;
    *(float4*)(g_AGG + (size_t)w * 128 + lane * 4) = a0;
    // HD = deg * H (self row)
    float dg = g_DEG[w];
    float4 h = *(const float4*)(base + (size_t)w * 128);
    h.x *= dg; h.y *= dg; h.z *= dg; h.w *= dg;
    *(float4*)(g_HD + (size_t)w * 128 + lane * 4) = h;
}

// ---------------- tf32 mma.sync GEMM, cp.async double-buffered ----------------
// MODE 0: pre-conv  (K=128; epilogue H=relu(x+bias))
// MODE 1: post-conv (stitched K=288 from HD|AGG|TAIL, relu)
// MODE 2: post-conv (stitched K=288, no relu)
#define GSMEM (4 * 4608 * 4)   // 73728 B: A0 A1 B0 B1

template <int MODE>
__device__ __forceinline__ void stage_chunk(const float* __restrict__ A,
                                            const float* __restrict__ Bimg,
                                            float* AsBuf, float* BsBuf,
                                            int c, int block_row, int n, int tid) {
    const int k0 = c * 32;
    const float* srcbase;
    int stride, off;
    if (MODE == 0)      { srcbase = A;      stride = 128; off = k0; }
    else if (k0 < 128)  { srcbase = g_HD;   stride = 128; off = k0; }
    else if (k0 < 256)  { srcbase = g_AGG;  stride = 128; off = k0 - 128; }
    else                { srcbase = g_TAIL; stride = 32;  off = 0; }
    #pragma unroll
    for (int l = 0; l < 4; l++) {
        int i = tid + l * 256;                 // 1024 = 128 rows x 8 float4
        int r = i >> 3, kq = (i & 7) << 2;
        int grow = block_row + r;
        uint32_t dst = (uint32_t)__cvta_generic_to_shared(AsBuf + r * 36 + kq);
        cpa16(dst, srcbase + (size_t)grow * stride + off + kq, grow < n ? 16 : 0);
    }
    const float4* bsrc = (const float4*)(Bimg + (size_t)c * 4608);
    #pragma unroll
    for (int l = 0; l < 5; l++) {
        int i = tid + l * 256;
        if (i < 1152) {
            uint32_t dst = (uint32_t)__cvta_generic_to_shared((float4*)BsBuf + i);
            cpa16(dst, bsrc + i, 16);
        }
    }
}

template <int MODE>
__global__ __launch_bounds__(256)
void gemm_mma_kernel(const float* __restrict__ A, const float* __restrict__ Bimg,
                     const float* __restrict__ bias, float* __restrict__ Cout, int n) {
    extern __shared__ __align__(16) float sm[];
    float* Asb[2] = { sm, sm + 4608 };
    float* Bsb[2] = { sm + 9216, sm + 13824 };
    const int tid = threadIdx.x, lane = tid & 31, wid = tid >> 5;
    const int g = lane >> 2, tg = lane & 3;
    const int wr = (wid & 1) * 64, wc = (wid >> 1) * 32;
    const int block_row = blockIdx.x * 128;
    const int CHUNKS = (MODE == 0) ? 4 : 9;

    float acc[4][4][4];
    #pragma unroll
    for (int t = 0; t < 4; t++)
        #pragma unroll
        for (int u = 0; u < 4; u++)
            #pragma unroll
            for (int v = 0; v < 4; v++) acc[t][u][v] = 0.f;

    stage_chunk<MODE>(A, Bimg, Asb[0], Bsb[0], 0, block_row, n, tid);
    CP_COMMIT();

    for (int c = 0; c < CHUNKS; c++) {
        const int cur = c & 1;
        if (c + 1 < CHUNKS)
            stage_chunk<MODE>(A, Bimg, Asb[(c + 1) & 1], Bsb[(c + 1) & 1],
                              c + 1, block_row, n, tid);
        CP_COMMIT();
        CP_WAIT1();
        __syncthreads();
        const float* As = Asb[cur];
        const float* Bs = Bsb[cur];
        #pragma unroll
        for (int ks = 0; ks < 4; ks++) {
            const int kb = ks * 8;
            uint32_t bfr[4][2];
            #pragma unroll
            for (int u = 0; u < 4; u++) {
                const int nn = wc + u * 8 + g;
                bfr[u][0] = __float_as_uint(Bs[nn * 36 + kb + tg]);
                bfr[u][1] = __float_as_uint(Bs[nn * 36 + kb + tg + 4]);
            }
            #pragma unroll
            for (int t = 0; t < 4; t++) {
                const int r0 = wr + t * 16 + g, r1 = r0 + 8;
                uint32_t a0 = f2tf(As[r0 * 36 + kb + tg]);
                uint32_t a1 = f2tf(As[r1 * 36 + kb + tg]);
                uint32_t a2 = f2tf(As[r0 * 36 + kb + tg + 4]);
                uint32_t a3 = f2tf(As[r1 * 36 + kb + tg + 4]);
                #pragma unroll
                for (int u = 0; u < 4; u++)
                    mma_tf32(acc[t][u], a0, a1, a2, a3, bfr[u][0], bfr[u][1]);
            }
        }
        __syncthreads();
    }
    // ---- epilogue ----
    #pragma unroll
    for (int t = 0; t < 4; t++) {
        const int r0 = block_row + wr + t * 16 + g, r1 = r0 + 8;
        #pragma unroll
        for (int u = 0; u < 4; u++) {
            const int col = wc + u * 8 + tg * 2;
            float2 v0 = make_float2(acc[t][u][0], acc[t][u][1]);
            float2 v1 = make_float2(acc[t][u][2], acc[t][u][3]);
            if (MODE == 0) {
                float2 b2 = *(const float2*)(bias + col);
                v0.x = fmaxf(v0.x + b2.x, 0.f); v0.y = fmaxf(v0.y + b2.y, 0.f);
                v1.x = fmaxf(v1.x + b2.x, 0.f); v1.y = fmaxf(v1.y + b2.y, 0.f);
            } else if (MODE == 1) {
                v0.x = fmaxf(v0.x, 0.f); v0.y = fmaxf(v0.y, 0.f);
                v1.x = fmaxf(v1.x, 0.f); v1.y = fmaxf(v1.y, 0.f);
            }
            if (r0 < n) *(float2*)(Cout + (size_t)r0 * 128 + col) = v0;
            if (r1 < n) *(float2*)(Cout + (size_t)r1 * 128 + col) = v1;
        }
    }
}

// ---------------- link-prediction head ----------------
__global__ __launch_bounds__(256)
void head_kernel(const float* __restrict__ X, const void* __restrict__ eli,
                 const float* __restrict__ lpW, const float* __restrict__ lpb,
                 float* __restrict__ out, int Q) {
    int w = (blockIdx.x * blockDim.x + threadIdx.x) >> 5;
    int lane = threadIdx.x & 31;
    if (w >= Q) return;
    float2 wa[4], wb[4];
    #pragma unroll
    for (int i = 0; i < 4; i++) {
        wa[i] = *(const float2*)(lpW + (size_t)(4 * lane + i) * 2);
        wb[i] = *(const float2*)(lpW + (size_t)(128 + 4 * lane + i) * 2);
    }
    int i0 = 0, i1 = 0;
    if (lane == 0) {
        if (g_q64) {
            i0 = (int)((const long long*)eli)[w];
            i1 = (int)((const long long*)eli)[(size_t)Q + w];
        } else {
            i0 = ((const int*)eli)[w];
            i1 = ((const int*)eli)[(size_t)Q + w];
        }
    }
    i0 = __shfl_sync(0xffffffffu, i0, 0);
    i1 = __shfl_sync(0xffffffffu, i1, 0);
    float4 a = *(const float4*)(X + (size_t)i0 * 128 + lane * 4);
    float4 b = *(const float4*)(X + (size_t)i1 * 128 + lane * 4);
    float p0 = a.x * wa[0].x + a.y * wa[1].x + a.z * wa[2].x + a.w * wa[3].x
             + b.x * wb[0].x + b.y * wb[1].x + b.z * wb[2].x + b.w * wb[3].x;
    float p1 = a.x * wa[0].y + a.y * wa[1].y + a.z * wa[2].y + a.w * wa[3].y
             + b.x * wb[0].y + b.y * wb[1].y + b.z * wb[2].y + b.w * wb[3].y;
    #pragma unroll
    for (int off = 16; off; off >>= 1) {
        p0 += __shfl_down_sync(0xffffffffu, p0, off);
        p1 += __shfl_down_sync(0xffffffffu, p1, off);
    }
    if (lane == 0) {
        out[(size_t)2 * w + 0] = p0 + lpb[0];
        out[(size_t)2 * w + 1] = p1 + lpb[1];
    }
}

// ---------------- launch ----------------
extern "C" void kernel_launch(void* const* d_in, const int* in_sizes, int n_in,
                              void* d_out, int out_size) {
    const float* node_feature = (const float*)d_in[0];
    const void*  edge_index   = d_in[1];
    const float* edge_feature = (const float*)d_in[2];
    const void*  eli          = d_in[3];
    const float* c1_pre_W = (const float*)d_in[4];
    const float* c1_pre_b = (const float*)d_in[5];
    const float* c1_msg_W = (const float*)d_in[6];
    const float* c1_msg_b = (const float*)d_in[7];
    const float* c2_pre_W = (const float*)d_in[8];
    const float* c2_pre_b = (const float*)d_in[9];
    const float* c2_msg_W = (const float*)d_in[10];
    const float* c2_msg_b = (const float*)d_in[11];
    const float* lp_W     = (const float*)d_in[12];
    const float* lp_b     = (const float*)d_in[13];
    float* out = (float*)d_out;

    const int N = in_sizes[0] / D;
    const int E = in_sizes[1] / 2;
    const int Q = in_sizes[3] / 2;

    float *H, *X, *Bpre, *Bpost;
    cudaGetSymbolAddress((void**)&H,  g_H);
    cudaGetSymbolAddress((void**)&X,  g_X);
    cudaGetSymbolAddress((void**)&Bpre, g_Bpre);
    cudaGetSymbolAddress((void**)&Bpost, g_Bpost);
    float* Bpre1  = Bpre;
    float* Bpre2  = Bpre + 4 * 4608;
    float* Bpost1 = Bpost;
    float* Bpost2 = Bpost + 9 * 4608;

    static int init_done = 0;
    static cudaStream_t s2;
    static cudaEvent_t evF, evJ;
    if (!init_done) {
        cudaFuncSetAttribute(gemm_mma_kernel<0>, cudaFuncAttributeMaxDynamicSharedMemorySize, GSMEM);
        cudaFuncSetAttribute(gemm_mma_kernel<1>, cudaFuncAttributeMaxDynamicSharedMemorySize, GSMEM);
        cudaFuncSetAttribute(gemm_mma_kernel<2>, cudaFuncAttributeMaxDynamicSharedMemorySize, GSMEM);
        cudaStreamCreateWithFlags(&s2, cudaStreamNonBlocking);
        cudaEventCreateWithFlags(&evF, cudaEventDisableTiming);
        cudaEventCreateWithFlags(&evJ, cudaEventDisableTiming);
        init_done = 1;
    }

    const int gemm_blocks  = (N + 127) / 128;
    const int warp8_blocks = (N + 7) / 8;
    const int edge_blocks  = (E + 255) / 256;
    const int nb = (N + 255) / 256;

    // root: zero counters + dtype detect
    detect_zero_kernel<<<nb, 256>>>((const int*)edge_index, (const int*)eli, N);

    // ---- fork: CSR build on side stream ----
    cudaEventRecord(evF, 0);
    cudaStreamWaitEvent(s2, evF, 0);
    hist_kernel<<<edge_blocks, 256, 0, s2>>>(edge_index, E);
    scan1_kernel<<<nb, 256, 0, s2>>>(N);
    scan2_kernel<<<1, 256, 0, s2>>>(nb);
    scan3_kernel<<<(N + 256) / 256, 256, 0, s2>>>(N, E);
    fill_kernel<<<edge_blocks, 256, 0, s2>>>(edge_index, E);
    eagg_tail_kernel<<<warp8_blocks, 256, 0, s2>>>(edge_feature, N);
    cudaEventRecord(evJ, s2);

    // ---- main stream: weight prep + layer-1 pre-GEMM (independent of CSR) ----
    prep_all_kernel<<<(106496 + 255) / 256, 256>>>(c1_pre_W, c2_pre_W,
                                                   c1_msg_W, c1_msg_b,
                                                   c2_msg_W, c2_msg_b,
                                                   Bpre1, Bpre2, Bpost1, Bpost2);
    gemm_mma_kernel<0><<<gemm_blocks, 256, GSMEM>>>(node_feature, Bpre1, c1_pre_b, H, N);

    // ---- join ----
    cudaStreamWaitEvent(0, evJ, 0);

    // layer 1 rest
    gather_agg_kernel<<<warp8_blocks, 256>>>(H, N);
    gemm_mma_kernel<1><<<gemm_blocks, 256, GSMEM>>>(H, Bpost1, nullptr, X, N);

    // layer 2
    gemm_mma_kernel<0><<<gemm_blocks, 256, GSMEM>>>(X, Bpre2, c2_pre_b, H, N);
    gather_agg_kernel<<<warp8_blocks, 256>>>(H, N);
    gemm_mma_kernel<2><<<gemm_blocks, 256, GSMEM>>>(H, Bpost2, nullptr, X, N);

    head_kernel<<<(Q + 7) / 8, 256>>>(X, eli, lp_W, lp_b, out, Q);
}

// round 6
// speedup vs baseline: 2.6236x; 1.0175x over previous
#include <cuda_runtime.h>
#include <cstdint>

#define NN 50000
#define EE 500000
#define D  128

// ---------------- device scratch (no allocation allowed) ----------------
__device__ float g_H[(size_t)NN * D];            // pre-conv output
__device__ float g_HD[(size_t)NN * D];           // deg * H (written by gather)
__device__ float g_X[(size_t)NN * D];            // conv output
__device__ float g_AGG[(size_t)NN * D];          // gathered neighbor sum
__device__ float g_TAIL[(size_t)NN * 32];        // [eagg(16) | deg | 0...]
__device__ float g_DEG[NN];
__device__ int   g_cnt[NN], g_cur[NN];
__device__ int   g_off[NN + 1];
__device__ int   g_srce[EE], g_eid[EE];
__device__ int   g_bsum[512], g_bsum2[512];
__device__ int   g_e64, g_q64;
// Pre-transposed, tf32-converted, fragment-layout B images.
__device__ float g_Bpre[2][4 * 4608];     // K=128 -> 4 chunks
__device__ float g_Bpost[2][9 * 4608];    // K=288 -> 9 chunks

// ---------------- helpers ----------------
__device__ __forceinline__ uint32_t f2tf(float x) {
    uint32_t o;
    asm("cvt.rna.tf32.f32 %0, %1;" : "=r"(o) : "f"(x));
    return o;
}
__device__ __forceinline__ float to_tf32(float x) { return __uint_as_float(f2tf(x)); }
__device__ __forceinline__ void mma_tf32(float* c, uint32_t a0, uint32_t a1,
                                         uint32_t a2, uint32_t a3,
                                         uint32_t b0, uint32_t b1) {
    asm volatile(
        "mma.sync.aligned.m16n8k8.row.col.f32.tf32.tf32.f32 "
        "{%0,%1,%2,%3}, {%4,%5,%6,%7}, {%8,%9}, {%0,%1,%2,%3};"
        : "+f"(c[0]), "+f"(c[1]), "+f"(c[2]), "+f"(c[3])
        : "r"(a0), "r"(a1), "r"(a2), "r"(a3), "r"(b0), "r"(b1));
}
__device__ __forceinline__ void cpa16(uint32_t dst, const void* src, int sz) {
    asm volatile("cp.async.cg.shared.global [%0], [%1], 16, %2;"
                 :: "r"(dst), "l"(src), "r"(sz) : "memory");
}
#define CP_COMMIT() asm volatile("cp.async.commit_group;" ::: "memory")
#define CP_WAIT1()  asm volatile("cp.async.wait_group 1;" ::: "memory")

// ---------------- fused detect (warp-parallel) + zero ----------------
__global__ void detect_zero_kernel(const int* __restrict__ ei, const int* __restrict__ eli, int n) {
    int i = blockIdx.x * blockDim.x + threadIdx.x;
    if (i < n) { g_cnt[i] = 0; g_cur[i] = 0; }
    if (blockIdx.x == 0 && threadIdx.x < 32) {
        int lane = threadIdx.x;
        int a = 0, b = 0;
        #pragma unroll
        for (int j = 0; j < 4; j++) {
            a |= ei[2 * (lane * 4 + j) + 1];
            b |= eli[2 * (lane * 4 + j) + 1];
        }
        unsigned ba = __ballot_sync(0xffffffffu, a != 0);
        unsigned bb = __ballot_sync(0xffffffffu, b != 0);
        if (lane == 0) {
            g_e64 = (ba == 0) ? 1 : 0;
            g_q64 = (bb == 0) ? 1 : 0;
        }
    }
}

// ---------------- fused B-image prep ----------------
__device__ __forceinline__ void prep_one(const float* W, const float* bias,
                                         float* img, int K_eff, int idx) {
    int n = idx & 127;
    int k = idx >> 7;
    float v = 0.f;
    if (k < K_eff) v = W[(size_t)k * 128 + n];
    else if (k == K_eff && bias != nullptr) v = bias[n];
    img[(size_t)(k >> 5) * 4608 + n * 36 + (k & 31)] = to_tf32(v);
}
__global__ void prep_all_kernel(const float* W1, const float* W2,
                                const float* W3, const float* b3,
                                const float* W4, const float* b4,
                                float* img1, float* img2, float* img3, float* img4) {
    int idx = blockIdx.x * blockDim.x + threadIdx.x;
    if (idx < 16384)       prep_one(W1, nullptr, img1, 128, idx);
    else if (idx < 32768)  prep_one(W2, nullptr, img2, 128, idx - 16384);
    else if (idx < 69632)  prep_one(W3, b3, img3, 272, idx - 32768);
    else if (idx < 106496) prep_one(W4, b4, img4, 272, idx - 69632);
}

// ---------------- CSR build ----------------
__global__ void hist_kernel(const void* __restrict__ ei, int E) {
    int e = blockIdx.x * blockDim.x + threadIdx.x;
    if (e >= E) return;
    int d = g_e64 ? (int)((const long long*)ei)[(size_t)E + e] : ((const int*)ei)[(size_t)E + e];
    atomicAdd(&g_cnt[d], 1);
}
__global__ void scan1_kernel(int n) {
    __shared__ int s[256];
    int idx = blockIdx.x * 256 + threadIdx.x;
    int v = (idx < n) ? g_cnt[idx] : 0;
    s[threadIdx.x] = v; __syncthreads();
    #pragma unroll
    for (int o = 1; o < 256; o <<= 1) {
        int t = (threadIdx.x >= o) ? s[threadIdx.x - o] : 0;
        __syncthreads(); s[threadIdx.x] += t; __syncthreads();
    }
    if (idx < n) g_off[idx] = s[threadIdx.x] - v;
    if (threadIdx.x == 255) g_bsum[blockIdx.x] = s[255];
}
// Warp-shuffle scan of up to 512 block sums (512 threads, 1 block).
__global__ void scan2_kernel(int nb) {
    __shared__ int wsum[16];
    int tid = threadIdx.x;            // 0..511
    int lane = tid & 31, wid = tid >> 5;
    int v = (tid < nb) ? g_bsum[tid] : 0;
    int x = v;
    #pragma unroll
    for (int o = 1; o < 32; o <<= 1) {
        int t = __shfl_up_sync(0xffffffffu, x, o);
        if (lane >= o) x += t;
    }
    if (lane == 31) wsum[wid] = x;
    __syncthreads();
    if (wid == 0) {
        int s = (lane < 16) ? wsum[lane] : 0;
        #pragma unroll
        for (int o = 1; o < 16; o <<= 1) {
            int t = __shfl_up_sync(0xffffffffu, s, o);
            if (lane >= o) s += t;
        }
        if (lane < 16) wsum[lane] = s;
    }
    __syncthreads();
    int base = (wid > 0) ? wsum[wid - 1] : 0;
    g_bsum2[tid] = base + x - v;      // exclusive
}
__global__ void scan3_kernel(int n, int E) {
    int idx = blockIdx.x * blockDim.x + threadIdx.x;
    if (idx < n) {
        g_off[idx] += g_bsum2[idx >> 8];
        g_DEG[idx] = (float)g_cnt[idx];
    }
    if (idx == n) g_off[n] = E;
}
__global__ void fill_kernel(const void* __restrict__ ei, int E) {
    int e = blockIdx.x * blockDim.x + threadIdx.x;
    if (e >= E) return;
    int s, d;
    if (g_e64) {
        s = (int)((const long long*)ei)[e];
        d = (int)((const long long*)ei)[(size_t)E + e];
    } else {
        s = ((const int*)ei)[e];
        d = ((const int*)ei)[(size_t)E + e];
    }
    int pos = g_off[d] + atomicAdd(&g_cur[d], 1);
    g_srce[pos] = s;
    g_eid[pos]  = e;
}
// eagg + TAIL pack: TAIL[w][0..15]=eagg, [16]=deg, [17..31]=0
__global__ __launch_bounds__(256)
void eagg_tail_kernel(const float* __restrict__ ef, int n) {
    int w = (blockIdx.x * blockDim.x + threadIdx.x) >> 5;
    int lane = threadIdx.x & 31;
    if (w >= n) return;
    int rs = g_off[w], re = g_off[w + 1];
    float acc = 0.f;
    if (lane < 16) {
        for (int j = rs; j < re; j++) {
            int e = __ldg(&g_eid[j]);
            acc += __ldg(ef + (size_t)e * 16 + lane);
        }
    } else if (lane == 16) {
        acc = g_DEG[w];
    }
    g_TAIL[(size_t)w * 32 + lane] = acc;
}

// ---------------- aggregation gather (atomic-free) + HD = deg*H ----------------
__global__ __launch_bounds__(256)
void gather_agg_kernel(const float* __restrict__ H, int n) {
    int w = (blockIdx.x * blockDim.x + threadIdx.x) >> 5;
    int lane = threadIdx.x & 31;
    if (w >= n) return;
    int rs = g_off[w], re = g_off[w + 1];
    float4 a0 = make_float4(0.f, 0.f, 0.f, 0.f);
    float4 a1 = make_float4(0.f, 0.f, 0.f, 0.f);
    const float* base = H + (size_t)lane * 4;
    int j = rs;
    for (; j + 1 < re; j += 2) {
        int s0 = __ldg(&g_srce[j]), s1 = __ldg(&g_srce[j + 1]);
        float4 v0 = *(const float4*)(base + (size_t)s0 * 128);
        float4 v1 = *(const float4*)(base + (size_t)s1 * 128);
        a0.x += v0.x; a0.y += v0.y; a0.z += v0.z; a0.w += v0.w;
        a1.x += v1.x; a1.y += v1.y; a1.z += v1.z; a1.w += v1.w;
    }
    if (j < re) {
        int s0 = __ldg(&g_srce[j]);
        float4 v0 = *(const float4*)(base + (size_t)s0 * 128);
        a0.x += v0.x; a0.y += v0.y; a0.z += v0.z; a0.w += v0.w;
    }
    a0.x += a1.x; a0.y += a1.y; a0.z += a1.z; a0.w += a1.w;
    *(float4*)(g_AGG + (size_t)w * 128 + lane * 4) = a0;
    float dg = g_DEG[w];
    float4 h = *(const float4*)(base + (size_t)w * 128);
    h.x *= dg; h.y *= dg; h.z *= dg; h.w *= dg;
    *(float4*)(g_HD + (size_t)w * 128 + lane * 4) = h;
}

// ---------------- tf32 mma.sync GEMM, cp.async double-buffered ----------------
#define GSMEM (4 * 4608 * 4)   // 73728 B: A0 A1 B0 B1

template <int MODE>
__device__ __forceinline__ void stage_chunk(const float* __restrict__ A,
                                            const float* __restrict__ Bimg,
                                            float* AsBuf, float* BsBuf,
                                            int c, int block_row, int n, int tid) {
    const int k0 = c * 32;
    const float* srcbase;
    int stride, off;
    if (MODE == 0)      { srcbase = A;      stride = 128; off = k0; }
    else if (k0 < 128)  { srcbase = g_HD;   stride = 128; off = k0; }
    else if (k0 < 256)  { srcbase = g_AGG;  stride = 128; off = k0 - 128; }
    else                { srcbase = g_TAIL; stride = 32;  off = 0; }
    #pragma unroll
    for (int l = 0; l < 4; l++) {
        int i = tid + l * 256;                 // 1024 = 128 rows x 8 float4
        int r = i >> 3, kq = (i & 7) << 2;
        int grow = block_row + r;
        uint32_t dst = (uint32_t)__cvta_generic_to_shared(AsBuf + r * 36 + kq);
        cpa16(dst, srcbase + (size_t)grow * stride + off + kq, grow < n ? 16 : 0);
    }
    const float4* bsrc = (const float4*)(Bimg + (size_t)c * 4608);
    #pragma unroll
    for (int l = 0; l < 5; l++) {
        int i = tid + l * 256;
        if (i < 1152) {
            uint32_t dst = (uint32_t)__cvta_generic_to_shared((float4*)BsBuf + i);
            cpa16(dst, bsrc + i, 16);
        }
    }
}

template <int MODE>
__global__ __launch_bounds__(256)
void gemm_mma_kernel(const float* __restrict__ A, const float* __restrict__ Bimg,
                     const float* __restrict__ bias, float* __restrict__ Cout, int n) {
    extern __shared__ __align__(16) float sm[];
    float* Asb[2] = { sm, sm + 4608 };
    float* Bsb[2] = { sm + 9216, sm + 13824 };
    const int tid = threadIdx.x, lane = tid & 31, wid = tid >> 5;
    const int g = lane >> 2, tg = lane & 3;
    const int wr = (wid & 1) * 64, wc = (wid >> 1) * 32;
    const int block_row = blockIdx.x * 128;
    const int CHUNKS = (MODE == 0) ? 4 : 9;

    float acc[4][4][4];
    #pragma unroll
    for (int t = 0; t < 4; t++)
        #pragma unroll
        for (int u = 0; u < 4; u++)
            #pragma unroll
            for (int v = 0; v < 4; v++) acc[t][u][v] = 0.f;

    stage_chunk<MODE>(A, Bimg, Asb[0], Bsb[0], 0, block_row, n, tid);
    CP_COMMIT();

    for (int c = 0; c < CHUNKS; c++) {
        const int cur = c & 1;
        if (c + 1 < CHUNKS)
            stage_chunk<MODE>(A, Bimg, Asb[(c + 1) & 1], Bsb[(c + 1) & 1],
                              c + 1, block_row, n, tid);
        CP_COMMIT();
        CP_WAIT1();
        __syncthreads();
        const float* As = Asb[cur];
        const float* Bs = Bsb[cur];
        #pragma unroll
        for (int ks = 0; ks < 4; ks++) {
            const int kb = ks * 8;
            uint32_t bfr[4][2];
            #pragma unroll
            for (int u = 0; u < 4; u++) {
                const int nn = wc + u * 8 + g;
                bfr[u][0] = __float_as_uint(Bs[nn * 36 + kb + tg]);
                bfr[u][1] = __float_as_uint(Bs[nn * 36 + kb + tg + 4]);
            }
            #pragma unroll
            for (int t = 0; t < 4; t++) {
                const int r0 = wr + t * 16 + g, r1 = r0 + 8;
                uint32_t a0 = f2tf(As[r0 * 36 + kb + tg]);
                uint32_t a1 = f2tf(As[r1 * 36 + kb + tg]);
                uint32_t a2 = f2tf(As[r0 * 36 + kb + tg + 4]);
                uint32_t a3 = f2tf(As[r1 * 36 + kb + tg + 4]);
                #pragma unroll
                for (int u = 0; u < 4; u++)
                    mma_tf32(acc[t][u], a0, a1, a2, a3, bfr[u][0], bfr[u][1]);
            }
        }
        __syncthreads();
    }
    // ---- epilogue ----
    #pragma unroll
    for (int t = 0; t < 4; t++) {
        const int r0 = block_row + wr + t * 16 + g, r1 = r0 + 8;
        #pragma unroll
        for (int u = 0; u < 4; u++) {
            const int col = wc + u * 8 + tg * 2;
            float2 v0 = make_float2(acc[t][u][0], acc[t][u][1]);
            float2 v1 = make_float2(acc[t][u][2], acc[t][u][3]);
            if (MODE == 0) {
                float2 b2 = *(const float2*)(bias + col);
                v0.x = fmaxf(v0.x + b2.x, 0.f); v0.y = fmaxf(v0.y + b2.y, 0.f);
                v1.x = fmaxf(v1.x + b2.x, 0.f); v1.y = fmaxf(v1.y + b2.y, 0.f);
            } else if (MODE == 1) {
                v0.x = fmaxf(v0.x, 0.f); v0.y = fmaxf(v0.y, 0.f);
                v1.x = fmaxf(v1.x, 0.f); v1.y = fmaxf(v1.y, 0.f);
            }
            if (r0 < n) *(float2*)(Cout + (size_t)r0 * 128 + col) = v0;
            if (r1 < n) *(float2*)(Cout + (size_t)r1 * 128 + col) = v1;
        }
    }
}

// ---------------- link-prediction head ----------------
__global__ __launch_bounds__(256)
void head_kernel(const float* __restrict__ X, const void* __restrict__ eli,
                 const float* __restrict__ lpW, const float* __restrict__ lpb,
                 float* __restrict__ out, int Q) {
    int w = (blockIdx.x * blockDim.x + threadIdx.x) >> 5;
    int lane = threadIdx.x & 31;
    if (w >= Q) return;
    float2 wa[4], wb[4];
    #pragma unroll
    for (int i = 0; i < 4; i++) {
        wa[i] = *(const float2*)(lpW + (size_t)(4 * lane + i) * 2);
        wb[i] = *(const float2*)(lpW + (size_t)(128 + 4 * lane + i) * 2);
    }
    int i0 = 0, i1 = 0;
    if (lane == 0) {
        if (g_q64) {
            i0 = (int)((const long long*)eli)[w];
            i1 = (int)((const long long*)eli)[(size_t)Q + w];
        } else {
            i0 = ((const int*)eli)[w];
            i1 = ((const int*)eli)[(size_t)Q + w];
        }
    }
    i0 = __shfl_sync(0xffffffffu, i0, 0);
    i1 = __shfl_sync(0xffffffffu, i1, 0);
    float4 a = *(const float4*)(X + (size_t)i0 * 128 + lane * 4);
    float4 b = *(const float4*)(X + (size_t)i1 * 128 + lane * 4);
    float p0 = a.x * wa[0].x + a.y * wa[1].x + a.z * wa[2].x + a.w * wa[3].x
             + b.x * wb[0].x + b.y * wb[1].x + b.z * wb[2].x + b.w * wb[3].x;
    float p1 = a.x * wa[0].y + a.y * wa[1].y + a.z * wa[2].y + a.w * wa[3].y
             + b.x * wb[0].y + b.y * wb[1].y + b.z * wb[2].y + b.w * wb[3].y;
    #pragma unroll
    for (int off = 16; off; off >>= 1) {
        p0 += __shfl_down_sync(0xffffffffu, p0, off);
        p1 += __shfl_down_sync(0xffffffffu, p1, off);
    }
    if (lane == 0) {
        out[(size_t)2 * w + 0] = p0 + lpb[0];
        out[(size_t)2 * w + 1] = p1 + lpb[1];
    }
}

// ---------------- launch ----------------
extern "C" void kernel_launch(void* const* d_in, const int* in_sizes, int n_in,
                              void* d_out, int out_size) {
    const float* node_feature = (const float*)d_in[0];
    const void*  edge_index   = d_in[1];
    const float* edge_feature = (const float*)d_in[2];
    const void*  eli          = d_in[3];
    const float* c1_pre_W = (const float*)d_in[4];
    const float* c1_pre_b = (const float*)d_in[5];
    const float* c1_msg_W = (const float*)d_in[6];
    const float* c1_msg_b = (const float*)d_in[7];
    const float* c2_pre_W = (const float*)d_in[8];
    const float* c2_pre_b = (const float*)d_in[9];
    const float* c2_msg_W = (const float*)d_in[10];
    const float* c2_msg_b = (const float*)d_in[11];
    const float* lp_W     = (const float*)d_in[12];
    const float* lp_b     = (const float*)d_in[13];
    float* out = (float*)d_out;

    const int N = in_sizes[0] / D;
    const int E = in_sizes[1] / 2;
    const int Q = in_sizes[3] / 2;

    float *H, *X, *Bpre, *Bpost;
    cudaGetSymbolAddress((void**)&H,  g_H);
    cudaGetSymbolAddress((void**)&X,  g_X);
    cudaGetSymbolAddress((void**)&Bpre, g_Bpre);
    cudaGetSymbolAddress((void**)&Bpost, g_Bpost);
    float* Bpre1  = Bpre;
    float* Bpre2  = Bpre + 4 * 4608;
    float* Bpost1 = Bpost;
    float* Bpost2 = Bpost + 9 * 4608;

    static int init_done = 0;
    static cudaStream_t s2;
    static cudaEvent_t evF, evFill, evEagg;
    if (!init_done) {
        cudaFuncSetAttribute(gemm_mma_kernel<0>, cudaFuncAttributeMaxDynamicSharedMemorySize, GSMEM);
        cudaFuncSetAttribute(gemm_mma_kernel<1>, cudaFuncAttributeMaxDynamicSharedMemorySize, GSMEM);
        cudaFuncSetAttribute(gemm_mma_kernel<2>, cudaFuncAttributeMaxDynamicSharedMemorySize, GSMEM);
        cudaStreamCreateWithFlags(&s2, cudaStreamNonBlocking);
        cudaEventCreateWithFlags(&evF, cudaEventDisableTiming);
        cudaEventCreateWithFlags(&evFill, cudaEventDisableTiming);
        cudaEventCreateWithFlags(&evEagg, cudaEventDisableTiming);
        init_done = 1;
    }

    const int gemm_blocks  = (N + 127) / 128;
    const int warp8_blocks = (N + 7) / 8;
    const int edge_blocks  = (E + 255) / 256;
    const int nb = (N + 255) / 256;

    // root: zero counters + dtype detect
    detect_zero_kernel<<<nb, 256>>>((const int*)edge_index, (const int*)eli, N);

    // ---- fork: CSR build on side stream ----
    cudaEventRecord(evF, 0);
    cudaStreamWaitEvent(s2, evF, 0);
    hist_kernel<<<edge_blocks, 256, 0, s2>>>(edge_index, E);
    scan1_kernel<<<nb, 256, 0, s2>>>(N);
    scan2_kernel<<<1, 512, 0, s2>>>(nb);
    scan3_kernel<<<(N + 256) / 256, 256, 0, s2>>>(N, E);
    fill_kernel<<<edge_blocks, 256, 0, s2>>>(edge_index, E);
    cudaEventRecord(evFill, s2);
    eagg_tail_kernel<<<warp8_blocks, 256, 0, s2>>>(edge_feature, N);   // runs concurrent with gather
    cudaEventRecord(evEagg, s2);

    // ---- main stream: weight prep + layer-1 pre-GEMM (independent of CSR) ----
    prep_all_kernel<<<(106496 + 255) / 256, 256>>>(c1_pre_W, c2_pre_W,
                                                   c1_msg_W, c1_msg_b,
                                                   c2_msg_W, c2_msg_b,
                                                   Bpre1, Bpre2, Bpost1, Bpost2);
    gemm_mma_kernel<0><<<gemm_blocks, 256, GSMEM>>>(node_feature, Bpre1, c1_pre_b, H, N);

    // ---- join 1: CSR arrays ready -> gather (concurrent with eagg on s2) ----
    cudaStreamWaitEvent(0, evFill, 0);
    gather_agg_kernel<<<warp8_blocks, 256>>>(H, N);

    // ---- join 2: TAIL ready -> post-GEMM ----
    cudaStreamWaitEvent(0, evEagg, 0);
    gemm_mma_kernel<1><<<gemm_blocks, 256, GSMEM>>>(H, Bpost1, nullptr, X, N);

    // layer 2
    gemm_mma_kernel<0><<<gemm_blocks, 256, GSMEM>>>(X, Bpre2, c2_pre_b, H, N);
    gather_agg_kernel<<<warp8_blocks, 256>>>(H, N);
    gemm_mma_kernel<2><<<gemm_blocks, 256, GSMEM>>>(H, Bpost2, nullptr, X, N);

    head_kernel<<<(Q + 7) / 8, 256>>>(X, eli, lp_W, lp_b, out, Q);
}